// round 1
// baseline (speedup 1.0000x reference)
#include <cuda_runtime.h>
#include <math.h>
#include <stdint.h>
#include <stddef.h>

// Problem constants
constexpr int B   = 2;
constexpr int T   = 768;
constexpr int KV  = 256;
constexpr int S   = 1024;   // T + KV
constexpr int D   = 1024;
constexpr int H   = 16;
constexpr int DH  = 64;
constexpr int L   = 6;
constexpr int V   = 32000;
constexpr int NTOK = B * S; // 2048
constexpr int PHYS_TOK = 5;

// ---------------- scratch (static device globals; no runtime allocation) ----
__device__ float g_x  [NTOK * D];        // residual stream
__device__ float g_h  [NTOK * D];        // LN output
__device__ float g_qkv[NTOK * 3 * D];    // fused qkv
__device__ float g_o  [NTOK * D];        // attention output (pre-proj)
__device__ float g_ff [NTOK * 4 * D];    // FF hidden
__device__ float g_att[(size_t)B * H * S * S]; // attention probs (134MB)
__device__ int   g_pe [B];

// ---------------- pe (first PHYS_TOK position + 1, else 0) ------------------
__global__ void pe_kernel(const int* __restrict__ idx) {
    int b = threadIdx.x;
    if (b < B) {
        int pe = 0;
        for (int s = 0; s < T; s++) {
            if (idx[b * T + s] == PHYS_TOK) { pe = s + 1; break; }
        }
        g_pe[b] = pe;
    }
}

// ---------------- embedding splice + positional ------------------------------
__global__ void embed_kernel(const int* __restrict__ idx,
                             const float* __restrict__ vis,
                             const float* __restrict__ wte,
                             const float* __restrict__ wpe) {
    int i = blockIdx.x * blockDim.x + threadIdx.x;   // over B*S*D
    int d = i & (D - 1);
    int p = (i / D) & (S - 1);
    int b = i / (D * S);
    int pe = g_pe[b];
    float v;
    if (p >= pe && p < pe + KV) {
        int vi = p - pe;                              // in [0, KV)
        v = vis[((size_t)b * KV + vi) * D + d];
    } else {
        int ti = (p < pe) ? p : (p - KV);
        ti = min(max(ti, 0), T - 1);
        v = wte[(size_t)idx[b * T + ti] * D + d];
    }
    g_x[i] = v + wpe[(size_t)p * D + d];
}

// ---------------- LayerNorm (one block per row of D=1024) -------------------
__global__ void ln_kernel(const float* __restrict__ in, float* __restrict__ out,
                          const float* __restrict__ w, const float* __restrict__ b) {
    int row = blockIdx.x;
    const float* x = in + (size_t)row * D;
    float v[4];
    float s = 0.f, s2 = 0.f;
#pragma unroll
    for (int u = 0; u < 4; u++) {
        v[u] = x[threadIdx.x + u * 256];
        s += v[u]; s2 += v[u] * v[u];
    }
#pragma unroll
    for (int o = 16; o; o >>= 1) {
        s  += __shfl_xor_sync(0xffffffffu, s,  o);
        s2 += __shfl_xor_sync(0xffffffffu, s2, o);
    }
    __shared__ float sh1[8], sh2[8];
    int wid = threadIdx.x >> 5, lid = threadIdx.x & 31;
    if (lid == 0) { sh1[wid] = s; sh2[wid] = s2; }
    __syncthreads();
    s = 0.f; s2 = 0.f;
#pragma unroll
    for (int wgi = 0; wgi < 8; wgi++) { s += sh1[wgi]; s2 += sh2[wgi]; }
    float mean = s * (1.f / D);
    float var  = s2 * (1.f / D) - mean * mean;
    float inv  = rsqrtf(var + 1e-5f);
    float* o = out + (size_t)row * D;
#pragma unroll
    for (int u = 0; u < 4; u++) {
        int j = threadIdx.x + u * 256;
        o[j] = (v[u] - mean) * inv * w[j] + b[j];
    }
}

// ---------------- generic SGEMM: C = A[M,K] * W[N,K]^T (+bias)(+gelu)(+res) --
// 128x128 block tile, BK=8, 256 threads, 8x8 per thread. All dims multiples
// of 128 (M=2048; N in {1024,3072,4096,32000}; K in {1024,4096}).
__device__ __forceinline__ float gelu_exact(float x) {
    return 0.5f * x * (1.f + erff(x * 0.70710678118654752f));
}

template<bool BIAS, bool GELU, bool RES>
__global__ __launch_bounds__(256)
void gemm_kernel(const float* __restrict__ A, const float* __restrict__ W,
                 const float* __restrict__ bias, const float* __restrict__ res,
                 float* __restrict__ C, int M, int N, int Kd) {
    __shared__ float As[8][128];
    __shared__ float Bs[8][128];
    int tid = threadIdx.x;
    int bm = blockIdx.y * 128;
    int bn = blockIdx.x * 128;
    int loadRow = tid >> 1;           // 0..127
    int loadCol = (tid & 1) * 4;      // 0 or 4
    const float* Ap = A + (size_t)(bm + loadRow) * Kd + loadCol;
    const float* Wp = W + (size_t)(bn + loadRow) * Kd + loadCol;
    int tx = tid & 15, ty = tid >> 4;
    float acc[8][8] = {};
    for (int k0 = 0; k0 < Kd; k0 += 8) {
        float4 a4 = *(const float4*)(Ap + k0);
        float4 w4 = *(const float4*)(Wp + k0);
        As[loadCol + 0][loadRow] = a4.x;
        As[loadCol + 1][loadRow] = a4.y;
        As[loadCol + 2][loadRow] = a4.z;
        As[loadCol + 3][loadRow] = a4.w;
        Bs[loadCol + 0][loadRow] = w4.x;
        Bs[loadCol + 1][loadRow] = w4.y;
        Bs[loadCol + 2][loadRow] = w4.z;
        Bs[loadCol + 3][loadRow] = w4.w;
        __syncthreads();
#pragma unroll
        for (int k = 0; k < 8; k++) {
            float4 ra0 = *(const float4*)&As[k][ty * 8];
            float4 ra1 = *(const float4*)&As[k][ty * 8 + 4];
            float4 rb0 = *(const float4*)&Bs[k][tx * 8];
            float4 rb1 = *(const float4*)&Bs[k][tx * 8 + 4];
            float ra[8] = {ra0.x, ra0.y, ra0.z, ra0.w, ra1.x, ra1.y, ra1.z, ra1.w};
            float rb[8] = {rb0.x, rb0.y, rb0.z, rb0.w, rb1.x, rb1.y, rb1.z, rb1.w};
#pragma unroll
            for (int i = 0; i < 8; i++)
#pragma unroll
                for (int j = 0; j < 8; j++)
                    acc[i][j] = fmaf(ra[i], rb[j], acc[i][j]);
        }
        __syncthreads();
    }
    int row0 = bm + ty * 8, col0 = bn + tx * 8;
#pragma unroll
    for (int i = 0; i < 8; i++) {
        float* crow = C + (size_t)(row0 + i) * N + col0;
        const float* rrow = res + (size_t)(row0 + i) * N + col0;
#pragma unroll
        for (int j4 = 0; j4 < 2; j4++) {
            float4 vv;
            vv.x = acc[i][j4 * 4 + 0];
            vv.y = acc[i][j4 * 4 + 1];
            vv.z = acc[i][j4 * 4 + 2];
            vv.w = acc[i][j4 * 4 + 3];
            if (BIAS) {
                vv.x += bias[col0 + j4 * 4 + 0];
                vv.y += bias[col0 + j4 * 4 + 1];
                vv.z += bias[col0 + j4 * 4 + 2];
                vv.w += bias[col0 + j4 * 4 + 3];
            }
            if (GELU) {
                vv.x = gelu_exact(vv.x); vv.y = gelu_exact(vv.y);
                vv.z = gelu_exact(vv.z); vv.w = gelu_exact(vv.w);
            }
            if (RES) {
                float4 r = *(const float4*)(rrow + j4 * 4);
                vv.x += r.x; vv.y += r.y; vv.z += r.z; vv.w += r.w;
            }
            *(float4*)(crow + j4 * 4) = vv;
        }
    }
}

// ---------------- attention scores: att = Q K^T * 1/8 + mask ----------------
// grid (S/64, S/64, B*H); 64x64 output tile per block, DH=64 fully in smem.
__global__ __launch_bounds__(256)
void scores_kernel(const float* __restrict__ qkv) {
    int bh = blockIdx.z;
    int b = bh >> 4, h = bh & 15;
    int qBase = blockIdx.y * 64;
    int kBase = blockIdx.x * 64;
    __shared__ float sQ[64][65];   // [d][row]
    __shared__ float sK[64][65];
    int tid = threadIdx.x;
    int row = tid >> 2;            // 0..63
    int seg = (tid & 3) * 16;      // 0,16,32,48
    const float* qp = qkv + (size_t)(b * S + qBase + row) * (3 * D) + h * DH + seg;
    const float* kp = qkv + (size_t)(b * S + kBase + row) * (3 * D) + D + h * DH + seg;
#pragma unroll
    for (int u = 0; u < 4; u++) {
        float4 q4 = *(const float4*)(qp + u * 4);
        float4 k4 = *(const float4*)(kp + u * 4);
        int d = seg + u * 4;
        sQ[d + 0][row] = q4.x; sQ[d + 1][row] = q4.y; sQ[d + 2][row] = q4.z; sQ[d + 3][row] = q4.w;
        sK[d + 0][row] = k4.x; sK[d + 1][row] = k4.y; sK[d + 2][row] = k4.z; sK[d + 3][row] = k4.w;
    }
    __syncthreads();
    int tx = tid & 15, ty = tid >> 4;
    float acc[4][4] = {};
#pragma unroll
    for (int d = 0; d < 64; d++) {
        float rq[4], rk[4];
#pragma unroll
        for (int i = 0; i < 4; i++) rq[i] = sQ[d][ty * 4 + i];
#pragma unroll
        for (int j = 0; j < 4; j++) rk[j] = sK[d][tx * 4 + j];
#pragma unroll
        for (int i = 0; i < 4; i++)
#pragma unroll
            for (int j = 0; j < 4; j++)
                acc[i][j] = fmaf(rq[i], rk[j], acc[i][j]);
    }
    int pe = g_pe[b], ve = pe + KV;
    float* out = g_att + ((size_t)bh << 20);
#pragma unroll
    for (int i = 0; i < 4; i++) {
#pragma unroll
        for (int j = 0; j < 4; j++) {
            int q  = qBase + ty * 4 + i;
            int kk = kBase + tx * 4 + j;
            bool allowed = (q < pe && kk < pe) ||
                           (q >= pe && q < ve && kk < ve) ||
                           (q >= ve && kk <= q);
            out[(size_t)q * S + kk] = acc[i][j] * 0.125f + (allowed ? 0.f : -1e9f);
        }
    }
}

// ---------------- softmax over last dim (one block per row of 1024) ---------
__global__ __launch_bounds__(256)
void softmax_kernel() {
    float* row = g_att + (size_t)blockIdx.x * S;
    int t = threadIdx.x;
    float v[4];
    float m = -3.4e38f;
#pragma unroll
    for (int u = 0; u < 4; u++) { v[u] = row[t + u * 256]; m = fmaxf(m, v[u]); }
#pragma unroll
    for (int o = 16; o; o >>= 1) m = fmaxf(m, __shfl_xor_sync(0xffffffffu, m, o));
    __shared__ float sh[8];
    int wid = t >> 5, lid = t & 31;
    if (lid == 0) sh[wid] = m;
    __syncthreads();
    m = sh[0];
#pragma unroll
    for (int wgi = 1; wgi < 8; wgi++) m = fmaxf(m, sh[wgi]);
    __syncthreads();
    float s = 0.f;
#pragma unroll
    for (int u = 0; u < 4; u++) { v[u] = __expf(v[u] - m); s += v[u]; }
#pragma unroll
    for (int o = 16; o; o >>= 1) s += __shfl_xor_sync(0xffffffffu, s, o);
    if (lid == 0) sh[wid] = s;
    __syncthreads();
    s = 0.f;
#pragma unroll
    for (int wgi = 0; wgi < 8; wgi++) s += sh[wgi];
    float inv = 1.f / s;
#pragma unroll
    for (int u = 0; u < 4; u++) row[t + u * 256] = v[u] * inv;
}

// ---------------- AV: O = att @ V  (64 q-rows x 64 d-cols per block) --------
__global__ __launch_bounds__(256)
void av_kernel(const float* __restrict__ qkv) {
    int bh = blockIdx.y;
    int b = bh >> 4, h = bh & 15;
    int qBase = blockIdx.x * 64;
    __shared__ float sA[64][68];   // [q][k]
    __shared__ float sV[64][68];   // [k][d]
    int tid = threadIdx.x;
    int row = tid >> 2;
    int seg = (tid & 3) * 16;
    int tx = tid & 15, ty = tid >> 4;
    float acc[4][4] = {};
    const float* arow = g_att + ((size_t)bh << 20) + (size_t)(qBase + row) * S + seg;
    const float* vbase = qkv + 2 * D + h * DH;
    for (int kc = 0; kc < S; kc += 64) {
#pragma unroll
        for (int u = 0; u < 4; u++) {
            float4 a4 = *(const float4*)(arow + kc + u * 4);
            *(float4*)&sA[row][seg + u * 4] = a4;
            float4 v4 = *(const float4*)(vbase + (size_t)(b * S + kc + row) * (3 * D) + seg + u * 4);
            *(float4*)&sV[row][seg + u * 4] = v4;
        }
        __syncthreads();
#pragma unroll
        for (int k = 0; k < 64; k++) {
            float ra[4], rv[4];
#pragma unroll
            for (int i = 0; i < 4; i++) ra[i] = sA[ty * 4 + i][k];
#pragma unroll
            for (int j = 0; j < 4; j++) rv[j] = sV[k][tx * 4 + j];
#pragma unroll
            for (int i = 0; i < 4; i++)
#pragma unroll
                for (int j = 0; j < 4; j++)
                    acc[i][j] = fmaf(ra[i], rv[j], acc[i][j]);
        }
        __syncthreads();
    }
#pragma unroll
    for (int i = 0; i < 4; i++)
#pragma unroll
        for (int j = 0; j < 4; j++)
            g_o[(size_t)(b * S + qBase + ty * 4 + i) * D + h * DH + tx * 4 + j] = acc[i][j];
}

// ---------------- host: launch sequence (graph-capturable) ------------------
extern "C" void kernel_launch(void* const* d_in, const int* in_sizes, int n_in,
                              void* d_out, int out_size) {
    const int*   idx    = (const int*)  d_in[0];
    const float* vis    = (const float*)d_in[1];
    const float* wte    = (const float*)d_in[2];
    const float* wpe    = (const float*)d_in[3];
    const float* qkv_w  = (const float*)d_in[4];
    const float* qkv_b  = (const float*)d_in[5];
    const float* out_w  = (const float*)d_in[6];
    const float* out_b  = (const float*)d_in[7];
    const float* ln1_w  = (const float*)d_in[8];
    const float* ln1_b  = (const float*)d_in[9];
    const float* ln2_w  = (const float*)d_in[10];
    const float* ln2_b  = (const float*)d_in[11];
    const float* ff1_w  = (const float*)d_in[12];
    const float* ff1_b  = (const float*)d_in[13];
    const float* ff2_w  = (const float*)d_in[14];
    const float* ff2_b  = (const float*)d_in[15];
    const float* lnf_w  = (const float*)d_in[16];
    const float* lnf_b  = (const float*)d_in[17];
    float* logits = (float*)d_out;

    float *px, *ph, *pqkv, *po, *pff;
    cudaGetSymbolAddress((void**)&px,   g_x);
    cudaGetSymbolAddress((void**)&ph,   g_h);
    cudaGetSymbolAddress((void**)&pqkv, g_qkv);
    cudaGetSymbolAddress((void**)&po,   g_o);
    cudaGetSymbolAddress((void**)&pff,  g_ff);

    pe_kernel<<<1, 32>>>(idx);
    embed_kernel<<<(NTOK * D) / 256, 256>>>(idx, vis, wte, wpe);

    for (int l = 0; l < L; l++) {
        const float* qw  = qkv_w + (size_t)l * 3 * D * D;
        const float* qb  = qkv_b + (size_t)l * 3 * D;
        const float* ow  = out_w + (size_t)l * D * D;
        const float* ob  = out_b + (size_t)l * D;
        const float* f1w = ff1_w + (size_t)l * 4 * D * D;
        const float* f1b = ff1_b + (size_t)l * 4 * D;
        const float* f2w = ff2_w + (size_t)l * D * 4 * D;
        const float* f2b = ff2_b + (size_t)l * D;

        ln_kernel<<<NTOK, 256>>>(px, ph, ln1_w + l * D, ln1_b + l * D);
        gemm_kernel<true, false, false><<<dim3(3 * D / 128, NTOK / 128), 256>>>(
            ph, qw, qb, nullptr, pqkv, NTOK, 3 * D, D);
        scores_kernel<<<dim3(S / 64, S / 64, B * H), 256>>>(pqkv);
        softmax_kernel<<<B * H * S, 256>>>();
        av_kernel<<<dim3(S / 64, B * H), 256>>>(pqkv);
        gemm_kernel<true, false, true><<<dim3(D / 128, NTOK / 128), 256>>>(
            po, ow, ob, px, px, NTOK, D, D);
        ln_kernel<<<NTOK, 256>>>(px, ph, ln2_w + l * D, ln2_b + l * D);
        gemm_kernel<true, true, false><<<dim3(4 * D / 128, NTOK / 128), 256>>>(
            ph, f1w, f1b, nullptr, pff, NTOK, 4 * D, D);
        gemm_kernel<true, false, true><<<dim3(D / 128, NTOK / 128), 256>>>(
            pff, f2w, f2b, px, px, NTOK, D, 4 * D);
    }

    ln_kernel<<<NTOK, 256>>>(px, ph, lnf_w, lnf_b);
    gemm_kernel<false, false, false><<<dim3(V / 128, NTOK / 128), 256>>>(
        ph, wte, nullptr, nullptr, logits, NTOK, V, D);
}

// round 4
// speedup vs baseline: 1.9968x; 1.9968x over previous
#include <cuda_runtime.h>
#include <cuda_bf16.h>
#include <math.h>
#include <stdint.h>
#include <stddef.h>

// Problem constants
constexpr int B   = 2;
constexpr int T   = 768;
constexpr int KV  = 256;
constexpr int S   = 1024;
constexpr int D   = 1024;
constexpr int H   = 16;
constexpr int DH  = 64;
constexpr int L   = 6;
constexpr int V   = 32000;
constexpr int NTOK = B * S;
constexpr int PHYS_TOK = 5;

// ---------------- fp32 scratch ----------------------------------------------
__device__ float g_x  [NTOK * D];
__device__ float g_h  [NTOK * D];
__device__ float g_qkv[NTOK * 3 * D];
__device__ float g_o  [NTOK * D];
__device__ float g_ff [NTOK * 4 * D];
__device__ float g_att[(size_t)B * H * S * S];
__device__ int   g_pe [B];

// ---------------- bf16 split (hi/lo) storage --------------------------------
__device__ __nv_bfloat16 w_qkv_h[L*3*D*D], w_qkv_l[L*3*D*D];
__device__ __nv_bfloat16 w_out_h[L*D*D],   w_out_l[L*D*D];
__device__ __nv_bfloat16 w_ff1_h[L*4*D*D], w_ff1_l[L*4*D*D];
__device__ __nv_bfloat16 w_ff2_h[L*4*D*D], w_ff2_l[L*4*D*D];
__device__ __nv_bfloat16 w_te_h [(size_t)V*D], w_te_l[(size_t)V*D];
__device__ __nv_bfloat16 a_h[NTOK*4*D],    a_l[NTOK*4*D];

// ============================ PTX helpers ====================================
__device__ __forceinline__ uint32_t smem_to_u32(const void* p) {
    uint32_t a;
    asm("{ .reg .u64 t; cvta.to.shared.u64 t, %1; cvt.u32.u64 %0, t; }" : "=r"(a) : "l"(p));
    return a;
}
__device__ __forceinline__ void ldmx4(uint32_t* r, uint32_t addr) {
    asm volatile("ldmatrix.sync.aligned.m8n8.x4.shared.b16 {%0,%1,%2,%3}, [%4];"
        : "=r"(r[0]), "=r"(r[1]), "=r"(r[2]), "=r"(r[3]) : "r"(addr));
}
__device__ __forceinline__ void mma16816(float* c, const uint32_t* a, const uint32_t* b) {
    asm volatile("mma.sync.aligned.m16n8k16.row.col.f32.bf16.bf16.f32 "
        "{%0,%1,%2,%3}, {%4,%5,%6,%7}, {%8,%9}, {%0,%1,%2,%3};"
        : "+f"(c[0]), "+f"(c[1]), "+f"(c[2]), "+f"(c[3])
        : "r"(a[0]), "r"(a[1]), "r"(a[2]), "r"(a[3]), "r"(b[0]), "r"(b[1]));
}

// ---------------- small kernels ----------------------------------------------
__global__ void pe_kernel(const int* __restrict__ idx) {
    int b = threadIdx.x;
    if (b < B) {
        int pe = 0;
        for (int s = 0; s < T; s++)
            if (idx[b * T + s] == PHYS_TOK) { pe = s + 1; break; }
        g_pe[b] = pe;
    }
}

__global__ void embed_kernel(const int* __restrict__ idx, const float* __restrict__ vis,
                             const float* __restrict__ wte, const float* __restrict__ wpe) {
    int i = blockIdx.x * blockDim.x + threadIdx.x;
    int d = i & (D - 1);
    int p = (i / D) & (S - 1);
    int b = i / (D * S);
    int pe = g_pe[b];
    float v;
    if (p >= pe && p < pe + KV) {
        v = vis[((size_t)b * KV + (p - pe)) * D + d];
    } else {
        int ti = (p < pe) ? p : (p - KV);
        ti = min(max(ti, 0), T - 1);
        v = wte[(size_t)idx[b * T + ti] * D + d];
    }
    g_x[i] = v + wpe[(size_t)p * D + d];
}

__global__ void ln_kernel(const float* __restrict__ in, float* __restrict__ out,
                          const float* __restrict__ w, const float* __restrict__ b) {
    int row = blockIdx.x;
    const float* x = in + (size_t)row * D;
    float v[4]; float s = 0.f, s2 = 0.f;
#pragma unroll
    for (int u = 0; u < 4; u++) { v[u] = x[threadIdx.x + u * 256]; s += v[u]; s2 += v[u] * v[u]; }
#pragma unroll
    for (int o = 16; o; o >>= 1) { s += __shfl_xor_sync(~0u, s, o); s2 += __shfl_xor_sync(~0u, s2, o); }
    __shared__ float sh1[8], sh2[8];
    int wid = threadIdx.x >> 5, lid = threadIdx.x & 31;
    if (lid == 0) { sh1[wid] = s; sh2[wid] = s2; }
    __syncthreads();
    s = 0.f; s2 = 0.f;
#pragma unroll
    for (int wg = 0; wg < 8; wg++) { s += sh1[wg]; s2 += sh2[wg]; }
    float mean = s * (1.f / D);
    float var  = s2 * (1.f / D) - mean * mean;
    float inv  = rsqrtf(var + 1e-5f);
    float* o = out + (size_t)row * D;
#pragma unroll
    for (int u = 0; u < 4; u++) {
        int j = threadIdx.x + u * 256;
        o[j] = (v[u] - mean) * inv * w[j] + b[j];
    }
}

// fp32 -> bf16 hi/lo split
__global__ void cvt_kernel(const float2* __restrict__ x, __nv_bfloat162* __restrict__ hi,
                           __nv_bfloat162* __restrict__ lo, int n2) {
    int i = blockIdx.x * blockDim.x + threadIdx.x;
    if (i >= n2) return;
    float2 v = x[i];
    __nv_bfloat162 h;
    h.x = __float2bfloat16(v.x);
    h.y = __float2bfloat16(v.y);
    float2 hf = make_float2(__bfloat162float(h.x), __bfloat162float(h.y));
    __nv_bfloat162 l;
    l.x = __float2bfloat16(v.x - hf.x);
    l.y = __float2bfloat16(v.y - hf.y);
    hi[i] = h; lo[i] = l;
}

__device__ __forceinline__ float gelu_exact(float x) {
    return 0.5f * x * (1.f + erff(x * 0.70710678118654752f));
}

// ================= mma.sync split-bf16 GEMM ==================================
// C[M,N] = (Ah+Al)[M,K] @ (Wh+Wl)[N,K]^T
// 128x128 CTA tile, BK=32, 256 threads (8 warps, 4x2), warp tile 32x64.
// 3 mma per tile per k16 (hh + hl + lh).
constexpr int LDSROW = 40; // 32 + 8 pad (bf16 elements)

__device__ __forceinline__ void ldg_tile(const __nv_bfloat16* __restrict__ src,
                                         int Kd, int k0, float4* r) {
    int tid = threadIdx.x;
#pragma unroll
    for (int i = 0; i < 2; i++) {
        int v = tid * 2 + i;
        int row = v >> 2, seg = v & 3;
        r[i] = *(const float4*)(src + (size_t)row * Kd + k0 + seg * 8);
    }
}
__device__ __forceinline__ void sts_tile(__nv_bfloat16* s, const float4* r) {
    int tid = threadIdx.x;
#pragma unroll
    for (int i = 0; i < 2; i++) {
        int v = tid * 2 + i;
        int row = v >> 2, seg = v & 3;
        *(float4*)(s + row * LDSROW + seg * 8) = r[i];
    }
}

template<bool BIAS, bool GELU, bool RES>
__global__ __launch_bounds__(256, 1)
void gemm_mma(const __nv_bfloat16* __restrict__ Ah, const __nv_bfloat16* __restrict__ Al,
              const __nv_bfloat16* __restrict__ Wh, const __nv_bfloat16* __restrict__ Wl,
              const float* __restrict__ bias, const float* __restrict__ res,
              float* __restrict__ C, int N, int Kd) {
    __shared__ __nv_bfloat16 sAh[128 * LDSROW];
    __shared__ __nv_bfloat16 sAl[128 * LDSROW];
    __shared__ __nv_bfloat16 sBh[128 * LDSROW];
    __shared__ __nv_bfloat16 sBl[128 * LDSROW];

    const int tid  = threadIdx.x;
    const int lane = tid & 31;
    const int wid  = tid >> 5;
    const int wm   = wid >> 1;          // 0..3 (M)
    const int wn   = wid & 1;           // 0..1 (N)
    const int bm   = blockIdx.x * 128;
    const int bn   = blockIdx.y * 128;

    const __nv_bfloat16* A0h = Ah + (size_t)bm * Kd;
    const __nv_bfloat16* A0l = Al + (size_t)bm * Kd;
    const __nv_bfloat16* W0h = Wh + (size_t)bn * Kd;
    const __nv_bfloat16* W0l = Wl + (size_t)bn * Kd;

    const uint32_t aAh = smem_to_u32(sAh), aAl = smem_to_u32(sAl);
    const uint32_t aBh = smem_to_u32(sBh), aBl = smem_to_u32(sBl);

    // ldmatrix lane address (16 rows x two 8-col halves), same for A and B tiles
    const uint32_t frag_lane = (uint32_t)((lane & 15) * LDSROW + (lane >> 4) * 8);

    float c[2][8][4];
#pragma unroll
    for (int mt = 0; mt < 2; mt++)
#pragma unroll
        for (int nt = 0; nt < 8; nt++)
#pragma unroll
            for (int q = 0; q < 4; q++) c[mt][nt][q] = 0.f;

    float4 rAh[2], rAl[2], rBh[2], rBl[2];
    ldg_tile(A0h, Kd, 0, rAh);
    ldg_tile(A0l, Kd, 0, rAl);
    ldg_tile(W0h, Kd, 0, rBh);
    ldg_tile(W0l, Kd, 0, rBl);

    const int nch = Kd / 32;
    for (int ch = 0; ch < nch; ch++) {
        sts_tile(sAh, rAh);
        sts_tile(sAl, rAl);
        sts_tile(sBh, rBh);
        sts_tile(sBl, rBl);
        __syncthreads();
        if (ch + 1 < nch) {
            int k0 = (ch + 1) * 32;
            ldg_tile(A0h, Kd, k0, rAh);
            ldg_tile(A0l, Kd, k0, rAl);
            ldg_tile(W0h, Kd, k0, rBh);
            ldg_tile(W0l, Kd, k0, rBl);
        }
#pragma unroll
        for (int ks = 0; ks < 2; ks++) {
            uint32_t ah[2][4], al[2][4], bh[8][2], bl[8][2];
#pragma unroll
            for (int mt = 0; mt < 2; mt++) {
                uint32_t off = ((uint32_t)((wm * 32 + mt * 16) * LDSROW + ks * 16) + frag_lane) * 2;
                ldmx4(ah[mt], aAh + off);
                ldmx4(al[mt], aAl + off);
            }
#pragma unroll
            for (int jj = 0; jj < 4; jj++) {
                uint32_t off = ((uint32_t)((wn * 64 + jj * 16) * LDSROW + ks * 16) + frag_lane) * 2;
                uint32_t t[4];
                // non-trans: matrices 0/1 = n-rows {0-7,8-15} of k0-7; 2/3 = same rows k8-15
                ldmx4(t, aBh + off);
                bh[jj * 2][0]     = t[0]; bh[jj * 2 + 1][0] = t[1];
                bh[jj * 2][1]     = t[2]; bh[jj * 2 + 1][1] = t[3];
                ldmx4(t, aBl + off);
                bl[jj * 2][0]     = t[0]; bl[jj * 2 + 1][0] = t[1];
                bl[jj * 2][1]     = t[2]; bl[jj * 2 + 1][1] = t[3];
            }
#pragma unroll
            for (int mt = 0; mt < 2; mt++)
#pragma unroll
                for (int nt = 0; nt < 8; nt++) {
                    mma16816(c[mt][nt], ah[mt], bh[nt]);
                    mma16816(c[mt][nt], ah[mt], bl[nt]);
                    mma16816(c[mt][nt], al[mt], bh[nt]);
                }
        }
        __syncthreads();
    }

    // epilogue: c frag layout (m16n8): c0,c1 -> (row=l>>2, col=(l&3)*2 +0/1); c2,c3 -> row+8
    const int row0 = bm + wm * 32;
    const int col0 = bn + wn * 64;
#pragma unroll
    for (int mt = 0; mt < 2; mt++) {
#pragma unroll
        for (int nt = 0; nt < 8; nt++) {
            int r  = row0 + mt * 16 + (lane >> 2);
            int cl = col0 + nt * 8 + (lane & 3) * 2;
#pragma unroll
            for (int half = 0; half < 2; half++) {
                int rr = r + half * 8;
                float v0 = c[mt][nt][half * 2];
                float v1 = c[mt][nt][half * 2 + 1];
                if (BIAS) { v0 += bias[cl]; v1 += bias[cl + 1]; }
                if (GELU) { v0 = gelu_exact(v0); v1 = gelu_exact(v1); }
                if (RES) {
                    const float* rp = res + (size_t)rr * N + cl;
                    v0 += rp[0]; v1 += rp[1];
                }
                float2 out = make_float2(v0, v1);
                *(float2*)(C + (size_t)rr * N + cl) = out;
            }
        }
    }
}

// ---------------- attention (fp32 SIMT) --------------------------------------
__global__ __launch_bounds__(256)
void scores_kernel(const float* __restrict__ qkv) {
    int bh = blockIdx.z;
    int b = bh >> 4, h = bh & 15;
    int qBase = blockIdx.y * 64;
    int kBase = blockIdx.x * 64;
    __shared__ float sQ[64][65];
    __shared__ float sK[64][65];
    int tid = threadIdx.x;
    int row = tid >> 2;
    int seg = (tid & 3) * 16;
    const float* qp = qkv + (size_t)(b * S + qBase + row) * (3 * D) + h * DH + seg;
    const float* kp = qkv + (size_t)(b * S + kBase + row) * (3 * D) + D + h * DH + seg;
#pragma unroll
    for (int u = 0; u < 4; u++) {
        float4 q4 = *(const float4*)(qp + u * 4);
        float4 k4 = *(const float4*)(kp + u * 4);
        int d = seg + u * 4;
        sQ[d + 0][row] = q4.x; sQ[d + 1][row] = q4.y; sQ[d + 2][row] = q4.z; sQ[d + 3][row] = q4.w;
        sK[d + 0][row] = k4.x; sK[d + 1][row] = k4.y; sK[d + 2][row] = k4.z; sK[d + 3][row] = k4.w;
    }
    __syncthreads();
    int tx = tid & 15, ty = tid >> 4;
    float acc[4][4] = {};
#pragma unroll
    for (int d = 0; d < 64; d++) {
        float rq[4], rk[4];
#pragma unroll
        for (int i = 0; i < 4; i++) rq[i] = sQ[d][ty * 4 + i];
#pragma unroll
        for (int j = 0; j < 4; j++) rk[j] = sK[d][tx * 4 + j];
#pragma unroll
        for (int i = 0; i < 4; i++)
#pragma unroll
            for (int j = 0; j < 4; j++)
                acc[i][j] = fmaf(rq[i], rk[j], acc[i][j]);
    }
    int pe = g_pe[b], ve = pe + KV;
    float* out = g_att + ((size_t)bh << 20);
#pragma unroll
    for (int i = 0; i < 4; i++) {
#pragma unroll
        for (int j = 0; j < 4; j++) {
            int q  = qBase + ty * 4 + i;
            int kk = kBase + tx * 4 + j;
            bool allowed = (q < pe && kk < pe) ||
                           (q >= pe && q < ve && kk < ve) ||
                           (q >= ve && kk <= q);
            out[(size_t)q * S + kk] = acc[i][j] * 0.125f + (allowed ? 0.f : -1e9f);
        }
    }
}

__global__ __launch_bounds__(256)
void softmax_kernel() {
    float* row = g_att + (size_t)blockIdx.x * S;
    int t = threadIdx.x;
    float v[4]; float m = -3.4e38f;
#pragma unroll
    for (int u = 0; u < 4; u++) { v[u] = row[t + u * 256]; m = fmaxf(m, v[u]); }
#pragma unroll
    for (int o = 16; o; o >>= 1) m = fmaxf(m, __shfl_xor_sync(~0u, m, o));
    __shared__ float sh[8];
    int wid = t >> 5, lid = t & 31;
    if (lid == 0) sh[wid] = m;
    __syncthreads();
    m = sh[0];
#pragma unroll
    for (int wg = 1; wg < 8; wg++) m = fmaxf(m, sh[wg]);
    __syncthreads();
    float s = 0.f;
#pragma unroll
    for (int u = 0; u < 4; u++) { v[u] = __expf(v[u] - m); s += v[u]; }
#pragma unroll
    for (int o = 16; o; o >>= 1) s += __shfl_xor_sync(~0u, s, o);
    if (lid == 0) sh[wid] = s;
    __syncthreads();
    s = 0.f;
#pragma unroll
    for (int wg = 0; wg < 8; wg++) s += sh[wg];
    float inv = 1.f / s;
#pragma unroll
    for (int u = 0; u < 4; u++) row[t + u * 256] = v[u] * inv;
}

__global__ __launch_bounds__(256)
void av_kernel(const float* __restrict__ qkv) {
    int bh = blockIdx.y;
    int b = bh >> 4, h = bh & 15;
    int qBase = blockIdx.x * 64;
    __shared__ float sA[64][68];
    __shared__ float sV[64][68];
    int tid = threadIdx.x;
    int row = tid >> 2;
    int seg = (tid & 3) * 16;
    int tx = tid & 15, ty = tid >> 4;
    float acc[4][4] = {};
    const float* arow = g_att + ((size_t)bh << 20) + (size_t)(qBase + row) * S + seg;
    const float* vbase = qkv + 2 * D + h * DH;
    for (int kc = 0; kc < S; kc += 64) {
#pragma unroll
        for (int u = 0; u < 4; u++) {
            float4 a4 = *(const float4*)(arow + kc + u * 4);
            *(float4*)&sA[row][seg + u * 4] = a4;
            float4 v4 = *(const float4*)(vbase + (size_t)(b * S + kc + row) * (3 * D) + seg + u * 4);
            *(float4*)&sV[row][seg + u * 4] = v4;
        }
        __syncthreads();
#pragma unroll
        for (int k = 0; k < 64; k++) {
            float ra[4], rv[4];
#pragma unroll
            for (int i = 0; i < 4; i++) ra[i] = sA[ty * 4 + i][k];
#pragma unroll
            for (int j = 0; j < 4; j++) rv[j] = sV[k][tx * 4 + j];
#pragma unroll
            for (int i = 0; i < 4; i++)
#pragma unroll
                for (int j = 0; j < 4; j++)
                    acc[i][j] = fmaf(ra[i], rv[j], acc[i][j]);
        }
        __syncthreads();
    }
#pragma unroll
    for (int i = 0; i < 4; i++)
#pragma unroll
        for (int j = 0; j < 4; j++)
            g_o[(size_t)(b * S + qBase + ty * 4 + i) * D + h * DH + tx * 4 + j] = acc[i][j];
}

// ---------------- host: launch sequence --------------------------------------
static inline void cvt(const float* x, __nv_bfloat16* hi, __nv_bfloat16* lo, size_t n) {
    int n2 = (int)(n / 2);
    cvt_kernel<<<(n2 + 255) / 256, 256>>>((const float2*)x, (__nv_bfloat162*)hi,
                                          (__nv_bfloat162*)lo, n2);
}

extern "C" void kernel_launch(void* const* d_in, const int* in_sizes, int n_in,
                              void* d_out, int out_size) {
    const int*   idx    = (const int*)  d_in[0];
    const float* vis    = (const float*)d_in[1];
    const float* wte    = (const float*)d_in[2];
    const float* wpe    = (const float*)d_in[3];
    const float* qkv_w  = (const float*)d_in[4];
    const float* qkv_b  = (const float*)d_in[5];
    const float* out_w  = (const float*)d_in[6];
    const float* out_b  = (const float*)d_in[7];
    const float* ln1_w  = (const float*)d_in[8];
    const float* ln1_b  = (const float*)d_in[9];
    const float* ln2_w  = (const float*)d_in[10];
    const float* ln2_b  = (const float*)d_in[11];
    const float* ff1_w  = (const float*)d_in[12];
    const float* ff1_b  = (const float*)d_in[13];
    const float* ff2_w  = (const float*)d_in[14];
    const float* ff2_b  = (const float*)d_in[15];
    const float* lnf_w  = (const float*)d_in[16];
    const float* lnf_b  = (const float*)d_in[17];
    float* logits = (float*)d_out;

    float *px, *ph, *pqkv, *po, *pff;
    cudaGetSymbolAddress((void**)&px,   g_x);
    cudaGetSymbolAddress((void**)&ph,   g_h);
    cudaGetSymbolAddress((void**)&pqkv, g_qkv);
    cudaGetSymbolAddress((void**)&po,   g_o);
    cudaGetSymbolAddress((void**)&pff,  g_ff);
    __nv_bfloat16 *pah, *pal, *pwqh, *pwql, *pwoh, *pwol, *pf1h, *pf1l, *pf2h, *pf2l, *pteh, *ptel;
    cudaGetSymbolAddress((void**)&pah,  a_h);
    cudaGetSymbolAddress((void**)&pal,  a_l);
    cudaGetSymbolAddress((void**)&pwqh, w_qkv_h);
    cudaGetSymbolAddress((void**)&pwql, w_qkv_l);
    cudaGetSymbolAddress((void**)&pwoh, w_out_h);
    cudaGetSymbolAddress((void**)&pwol, w_out_l);
    cudaGetSymbolAddress((void**)&pf1h, w_ff1_h);
    cudaGetSymbolAddress((void**)&pf1l, w_ff1_l);
    cudaGetSymbolAddress((void**)&pf2h, w_ff2_h);
    cudaGetSymbolAddress((void**)&pf2l, w_ff2_l);
    cudaGetSymbolAddress((void**)&pteh, w_te_h);
    cudaGetSymbolAddress((void**)&ptel, w_te_l);

    // weight conversions (fp32 -> bf16 hi/lo)
    cvt(qkv_w, pwqh, pwql, (size_t)L * 3 * D * D);
    cvt(out_w, pwoh, pwol, (size_t)L * D * D);
    cvt(ff1_w, pf1h, pf1l, (size_t)L * 4 * D * D);
    cvt(ff2_w, pf2h, pf2l, (size_t)L * 4 * D * D);
    cvt(wte,   pteh, ptel, (size_t)V * D);

    pe_kernel<<<1, 32>>>(idx);
    embed_kernel<<<(NTOK * D) / 256, 256>>>(idx, vis, wte, wpe);

    for (int l = 0; l < L; l++) {
        const __nv_bfloat16* qwh = pwqh + (size_t)l * 3 * D * D;
        const __nv_bfloat16* qwl = pwql + (size_t)l * 3 * D * D;
        const __nv_bfloat16* owh = pwoh + (size_t)l * D * D;
        const __nv_bfloat16* owl = pwol + (size_t)l * D * D;
        const __nv_bfloat16* f1h = pf1h + (size_t)l * 4 * D * D;
        const __nv_bfloat16* f1l = pf1l + (size_t)l * 4 * D * D;
        const __nv_bfloat16* f2h = pf2h + (size_t)l * 4 * D * D;
        const __nv_bfloat16* f2l = pf2l + (size_t)l * 4 * D * D;
        const float* qb  = qkv_b + (size_t)l * 3 * D;
        const float* ob  = out_b + (size_t)l * D;
        const float* f1b = ff1_b + (size_t)l * 4 * D;
        const float* f2b = ff2_b + (size_t)l * D;

        ln_kernel<<<NTOK, 256>>>(px, ph, ln1_w + l * D, ln1_b + l * D);
        cvt(ph, pah, pal, (size_t)NTOK * D);
        gemm_mma<true, false, false><<<dim3(NTOK / 128, 3 * D / 128), 256>>>(
            pah, pal, qwh, qwl, qb, nullptr, pqkv, 3 * D, D);

        scores_kernel<<<dim3(S / 64, S / 64, B * H), 256>>>(pqkv);
        softmax_kernel<<<B * H * S, 256>>>();
        av_kernel<<<dim3(S / 64, B * H), 256>>>(pqkv);

        cvt(po, pah, pal, (size_t)NTOK * D);
        gemm_mma<true, false, true><<<dim3(NTOK / 128, D / 128), 256>>>(
            pah, pal, owh, owl, ob, px, px, D, D);

        ln_kernel<<<NTOK, 256>>>(px, ph, ln2_w + l * D, ln2_b + l * D);
        cvt(ph, pah, pal, (size_t)NTOK * D);
        gemm_mma<true, true, false><<<dim3(NTOK / 128, 4 * D / 128), 256>>>(
            pah, pal, f1h, f1l, f1b, nullptr, pff, 4 * D, D);

        cvt(pff, pah, pal, (size_t)NTOK * 4 * D);
        gemm_mma<true, false, true><<<dim3(NTOK / 128, D / 128), 256>>>(
            pah, pal, f2h, f2l, f2b, px, px, D, 4 * D);
    }

    ln_kernel<<<NTOK, 256>>>(px, ph, lnf_w, lnf_b);
    cvt(ph, pah, pal, (size_t)NTOK * D);
    gemm_mma<false, false, false><<<dim3(NTOK / 128, V / 128), 256>>>(
        pah, pal, pteh, ptel, nullptr, nullptr, logits, V, D);
}

// round 6
// speedup vs baseline: 2.0086x; 1.0059x over previous
#include <cuda_runtime.h>
#include <cuda_bf16.h>
#include <math.h>
#include <stdint.h>
#include <stddef.h>

// Problem constants
constexpr int B   = 2;
constexpr int T   = 768;
constexpr int KV  = 256;
constexpr int S   = 1024;
constexpr int D   = 1024;
constexpr int H   = 16;
constexpr int DH  = 64;
constexpr int L   = 6;
constexpr int V   = 32000;
constexpr int NTOK = B * S;
constexpr int PHYS_TOK = 5;

// ---------------- fp32 scratch ----------------------------------------------
__device__ float g_x  [NTOK * D];
__device__ float g_qkv[NTOK * 3 * D];
__device__ float g_att[(size_t)B * H * S * S];
__device__ int   g_pe [B];

// ---------------- bf16 split (hi/lo) storage --------------------------------
__device__ __nv_bfloat16 w_qkv_h[L*3*D*D], w_qkv_l[L*3*D*D];
__device__ __nv_bfloat16 w_out_h[L*D*D],   w_out_l[L*D*D];
__device__ __nv_bfloat16 w_ff1_h[L*4*D*D], w_ff1_l[L*4*D*D];
__device__ __nv_bfloat16 w_ff2_h[L*4*D*D], w_ff2_l[L*4*D*D];
__device__ __nv_bfloat16 w_te_h [(size_t)V*D], w_te_l[(size_t)V*D];
__device__ __nv_bfloat16 a_h [NTOK*D],     a_l [NTOK*D];     // activations [NTOK,D]
__device__ __nv_bfloat16 a2_h[NTOK*4*D],   a2_l[NTOK*4*D];   // FF hidden   [NTOK,4D]

// ============================ PTX helpers ====================================
__device__ __forceinline__ uint32_t smem_to_u32(const void* p) {
    uint32_t a;
    asm("{ .reg .u64 t; cvta.to.shared.u64 t, %1; cvt.u32.u64 %0, t; }" : "=r"(a) : "l"(p));
    return a;
}
__device__ __forceinline__ void ldmx4(uint32_t* r, uint32_t addr) {
    asm volatile("ldmatrix.sync.aligned.m8n8.x4.shared.b16 {%0,%1,%2,%3}, [%4];"
        : "=r"(r[0]), "=r"(r[1]), "=r"(r[2]), "=r"(r[3]) : "r"(addr));
}
__device__ __forceinline__ void mma16816(float* c, const uint32_t* a, const uint32_t* b) {
    asm volatile("mma.sync.aligned.m16n8k16.row.col.f32.bf16.bf16.f32 "
        "{%0,%1,%2,%3}, {%4,%5,%6,%7}, {%8,%9}, {%0,%1,%2,%3};"
        : "+f"(c[0]), "+f"(c[1]), "+f"(c[2]), "+f"(c[3])
        : "r"(a[0]), "r"(a[1]), "r"(a[2]), "r"(a[3]), "r"(b[0]), "r"(b[1]));
}
__device__ __forceinline__ void cp16(uint32_t dst, const void* src) {
    asm volatile("cp.async.cg.shared.global [%0], [%1], 16;" :: "r"(dst), "l"(src));
}
__device__ __forceinline__ void cp_commit() {
    asm volatile("cp.async.commit_group;" ::: "memory");
}
template<int N>
__device__ __forceinline__ void cp_wait() {
    asm volatile("cp.async.wait_group %0;" :: "n"(N) : "memory");
}

// ---------------- small kernels ----------------------------------------------
__global__ void pe_kernel(const int* __restrict__ idx) {
    int b = threadIdx.x;
    if (b < B) {
        int pe = 0;
        for (int s = 0; s < T; s++)
            if (idx[b * T + s] == PHYS_TOK) { pe = s + 1; break; }
        g_pe[b] = pe;
    }
}

__global__ void embed_kernel(const int* __restrict__ idx, const float* __restrict__ vis,
                             const float* __restrict__ wte, const float* __restrict__ wpe) {
    int i = blockIdx.x * blockDim.x + threadIdx.x;
    int d = i & (D - 1);
    int p = (i / D) & (S - 1);
    int b = i / (D * S);
    int pe = g_pe[b];
    float v;
    if (p >= pe && p < pe + KV) {
        v = vis[((size_t)b * KV + (p - pe)) * D + d];
    } else {
        int ti = (p < pe) ? p : (p - KV);
        ti = min(max(ti, 0), T - 1);
        v = wte[(size_t)idx[b * T + ti] * D + d];
    }
    g_x[i] = v + wpe[(size_t)p * D + d];
}

// LayerNorm with fused hi/lo split output
__global__ void ln_split_kernel(const float* __restrict__ in,
                                const float* __restrict__ w, const float* __restrict__ b,
                                __nv_bfloat16* __restrict__ oh, __nv_bfloat16* __restrict__ ol) {
    int row = blockIdx.x;
    const float* x = in + (size_t)row * D;
    float v[4]; float s = 0.f, s2 = 0.f;
#pragma unroll
    for (int u = 0; u < 4; u++) { v[u] = x[threadIdx.x + u * 256]; s += v[u]; s2 += v[u] * v[u]; }
#pragma unroll
    for (int o = 16; o; o >>= 1) { s += __shfl_xor_sync(~0u, s, o); s2 += __shfl_xor_sync(~0u, s2, o); }
    __shared__ float sh1[8], sh2[8];
    int wid = threadIdx.x >> 5, lid = threadIdx.x & 31;
    if (lid == 0) { sh1[wid] = s; sh2[wid] = s2; }
    __syncthreads();
    s = 0.f; s2 = 0.f;
#pragma unroll
    for (int wg = 0; wg < 8; wg++) { s += sh1[wg]; s2 += sh2[wg]; }
    float mean = s * (1.f / D);
    float var  = s2 * (1.f / D) - mean * mean;
    float inv  = rsqrtf(var + 1e-5f);
#pragma unroll
    for (int u = 0; u < 4; u++) {
        int j = threadIdx.x + u * 256;
        float y = (v[u] - mean) * inv * w[j] + b[j];
        __nv_bfloat16 h = __float2bfloat16(y);
        oh[(size_t)row * D + j] = h;
        ol[(size_t)row * D + j] = __float2bfloat16(y - __bfloat162float(h));
    }
}

// fp32 -> bf16 hi/lo split (weights)
__global__ void cvt_kernel(const float2* __restrict__ x, __nv_bfloat162* __restrict__ hi,
                           __nv_bfloat162* __restrict__ lo, int n2) {
    int i = blockIdx.x * blockDim.x + threadIdx.x;
    if (i >= n2) return;
    float2 v = x[i];
    __nv_bfloat162 h;
    h.x = __float2bfloat16(v.x);
    h.y = __float2bfloat16(v.y);
    float2 hf = make_float2(__bfloat162float(h.x), __bfloat162float(h.y));
    __nv_bfloat162 l;
    l.x = __float2bfloat16(v.x - hf.x);
    l.y = __float2bfloat16(v.y - hf.y);
    hi[i] = h; lo[i] = l;
}

__device__ __forceinline__ float gelu_exact(float x) {
    return 0.5f * x * (1.f + erff(x * 0.70710678118654752f));
}

// ================= mma.sync split-bf16 GEMM, cp.async double-buffered ========
// C[M,N] = (Ah+Al)[M,K] @ (Wh+Wl)[N,K]^T
// 128x128 CTA tile, BK=32, 256 threads (8 warps 4x2), warp tile 32x64.
constexpr int LDSROW = 40;                    // 32 + 8 pad (bf16 elems)
constexpr int TILE_BYTES = 128 * LDSROW * 2;  // 10240
constexpr int BUF_BYTES  = 4 * TILE_BYTES;    // 40960
constexpr int GEMM_SMEM  = 2 * BUF_BYTES;     // 81920

__device__ __forceinline__ void cp_tile(uint32_t dst, const __nv_bfloat16* __restrict__ src,
                                        int Kd, int k0) {
    int tid = threadIdx.x;
#pragma unroll
    for (int i = 0; i < 2; i++) {
        int v = tid * 2 + i;
        int row = v >> 2, seg = v & 3;
        cp16(dst + (uint32_t)(row * LDSROW + seg * 8) * 2,
             src + (size_t)row * Kd + k0 + seg * 8);
    }
}

template<bool BIAS, bool GELU, bool RES, bool SPLIT>
__global__ __launch_bounds__(256, 2)
void gemm_mma(const __nv_bfloat16* __restrict__ Ah, const __nv_bfloat16* __restrict__ Al,
              const __nv_bfloat16* __restrict__ Wh, const __nv_bfloat16* __restrict__ Wl,
              const float* __restrict__ bias, const float* __restrict__ res,
              float* __restrict__ C, __nv_bfloat16* __restrict__ Ch,
              __nv_bfloat16* __restrict__ Cl, int N, int Kd) {
    extern __shared__ char smem[];
    const uint32_t sbase = smem_to_u32(smem);

    const int tid  = threadIdx.x;
    const int lane = tid & 31;
    const int wid  = tid >> 5;
    const int wm   = wid >> 1;
    const int wn   = wid & 1;
    const int bm   = blockIdx.x * 128;
    const int bn   = blockIdx.y * 128;

    const __nv_bfloat16* A0h = Ah + (size_t)bm * Kd;
    const __nv_bfloat16* A0l = Al + (size_t)bm * Kd;
    const __nv_bfloat16* W0h = Wh + (size_t)bn * Kd;
    const __nv_bfloat16* W0l = Wl + (size_t)bn * Kd;

    const uint32_t frag_lane = (uint32_t)((lane & 15) * LDSROW + (lane >> 4) * 8);
    const int nch = Kd / 32;

    auto issue = [&](int ch) {
        uint32_t b = sbase + (uint32_t)(ch & 1) * BUF_BYTES;
        int k0 = ch * 32;
        cp_tile(b,                  A0h, Kd, k0);
        cp_tile(b + TILE_BYTES,     A0l, Kd, k0);
        cp_tile(b + 2 * TILE_BYTES, W0h, Kd, k0);
        cp_tile(b + 3 * TILE_BYTES, W0l, Kd, k0);
        cp_commit();
    };

    float c[2][8][4];
#pragma unroll
    for (int mt = 0; mt < 2; mt++)
#pragma unroll
        for (int nt = 0; nt < 8; nt++)
#pragma unroll
            for (int q = 0; q < 4; q++) c[mt][nt][q] = 0.f;

    issue(0);
    if (nch > 1) issue(1);

    for (int ch = 0; ch < nch; ch++) {
        if (ch < nch - 1) cp_wait<1>(); else cp_wait<0>();
        __syncthreads();
        uint32_t b = sbase + (uint32_t)(ch & 1) * BUF_BYTES;
#pragma unroll
        for (int ks = 0; ks < 2; ks++) {
            uint32_t ah[2][4], al[2][4];
#pragma unroll
            for (int mt = 0; mt < 2; mt++) {
                uint32_t off = ((uint32_t)((wm * 32 + mt * 16) * LDSROW + ks * 16) + frag_lane) * 2;
                ldmx4(ah[mt], b + off);
                ldmx4(al[mt], b + TILE_BYTES + off);
            }
#pragma unroll
            for (int jj = 0; jj < 4; jj++) {
                uint32_t off = ((uint32_t)((wn * 64 + jj * 16) * LDSROW + ks * 16) + frag_lane) * 2;
                uint32_t th[4], tl[4];
                ldmx4(th, b + 2 * TILE_BYTES + off);
                ldmx4(tl, b + 3 * TILE_BYTES + off);
                uint32_t bh0[2] = { th[0], th[2] }, bh1[2] = { th[1], th[3] };
                uint32_t bl0[2] = { tl[0], tl[2] }, bl1[2] = { tl[1], tl[3] };
#pragma unroll
                for (int mt = 0; mt < 2; mt++) {
                    mma16816(c[mt][jj * 2],     ah[mt], bh0);
                    mma16816(c[mt][jj * 2],     ah[mt], bl0);
                    mma16816(c[mt][jj * 2],     al[mt], bh0);
                    mma16816(c[mt][jj * 2 + 1], ah[mt], bh1);
                    mma16816(c[mt][jj * 2 + 1], ah[mt], bl1);
                    mma16816(c[mt][jj * 2 + 1], al[mt], bh1);
                }
            }
        }
        __syncthreads();
        if (ch + 2 < nch) issue(ch + 2);
    }

    // epilogue: m16n8 frag: c0,c1 -> (row=l>>2, col=(l&3)*2+{0,1}); c2,c3 -> row+8
    const int row0 = bm + wm * 32;
    const int col0 = bn + wn * 64;
#pragma unroll
    for (int mt = 0; mt < 2; mt++) {
#pragma unroll
        for (int nt = 0; nt < 8; nt++) {
            int r  = row0 + mt * 16 + (lane >> 2);
            int cl = col0 + nt * 8 + (lane & 3) * 2;
#pragma unroll
            for (int half = 0; half < 2; half++) {
                int rr = r + half * 8;
                float v0 = c[mt][nt][half * 2];
                float v1 = c[mt][nt][half * 2 + 1];
                if (BIAS) { v0 += bias[cl]; v1 += bias[cl + 1]; }
                if (GELU) { v0 = gelu_exact(v0); v1 = gelu_exact(v1); }
                if (RES) {
                    const float* rp = res + (size_t)rr * N + cl;
                    v0 += rp[0]; v1 += rp[1];
                }
                if (SPLIT) {
                    __nv_bfloat162 hh, ll;
                    hh.x = __float2bfloat16(v0);
                    hh.y = __float2bfloat16(v1);
                    ll.x = __float2bfloat16(v0 - __bfloat162float(hh.x));
                    ll.y = __float2bfloat16(v1 - __bfloat162float(hh.y));
                    *(__nv_bfloat162*)(Ch + (size_t)rr * N + cl) = hh;
                    *(__nv_bfloat162*)(Cl + (size_t)rr * N + cl) = ll;
                } else {
                    *(float2*)(C + (size_t)rr * N + cl) = make_float2(v0, v1);
                }
            }
        }
    }
}

// ---------------- attention (fp32 SIMT) --------------------------------------
__global__ __launch_bounds__(256)
void scores_kernel(const float* __restrict__ qkv) {
    int bh = blockIdx.z;
    int b = bh >> 4, h = bh & 15;
    int qBase = blockIdx.y * 64;
    int kBase = blockIdx.x * 64;
    __shared__ float sQ[64][65];
    __shared__ float sK[64][65];
    int tid = threadIdx.x;
    int row = tid >> 2;
    int seg = (tid & 3) * 16;
    const float* qp = qkv + (size_t)(b * S + qBase + row) * (3 * D) + h * DH + seg;
    const float* kp = qkv + (size_t)(b * S + kBase + row) * (3 * D) + D + h * DH + seg;
#pragma unroll
    for (int u = 0; u < 4; u++) {
        float4 q4 = *(const float4*)(qp + u * 4);
        float4 k4 = *(const float4*)(kp + u * 4);
        int d = seg + u * 4;
        sQ[d + 0][row] = q4.x; sQ[d + 1][row] = q4.y; sQ[d + 2][row] = q4.z; sQ[d + 3][row] = q4.w;
        sK[d + 0][row] = k4.x; sK[d + 1][row] = k4.y; sK[d + 2][row] = k4.z; sK[d + 3][row] = k4.w;
    }
    __syncthreads();
    int tx = tid & 15, ty = tid >> 4;
    float acc[4][4] = {};
#pragma unroll
    for (int d = 0; d < 64; d++) {
        float rq[4], rk[4];
#pragma unroll
        for (int i = 0; i < 4; i++) rq[i] = sQ[d][ty * 4 + i];
#pragma unroll
        for (int j = 0; j < 4; j++) rk[j] = sK[d][tx * 4 + j];
#pragma unroll
        for (int i = 0; i < 4; i++)
#pragma unroll
            for (int j = 0; j < 4; j++)
                acc[i][j] = fmaf(rq[i], rk[j], acc[i][j]);
    }
    int pe = g_pe[b], ve = pe + KV;
    float* out = g_att + ((size_t)bh << 20);
#pragma unroll
    for (int i = 0; i < 4; i++) {
#pragma unroll
        for (int j = 0; j < 4; j++) {
            int q  = qBase + ty * 4 + i;
            int kk = kBase + tx * 4 + j;
            bool allowed = (q < pe && kk < pe) ||
                           (q >= pe && q < ve && kk < ve) ||
                           (q >= ve && kk <= q);
            out[(size_t)q * S + kk] = acc[i][j] * 0.125f + (allowed ? 0.f : -1e9f);
        }
    }
}

__global__ __launch_bounds__(256)
void softmax_kernel() {
    float* row = g_att + (size_t)blockIdx.x * S;
    int t = threadIdx.x;
    float v[4]; float m = -3.4e38f;
#pragma unroll
    for (int u = 0; u < 4; u++) { v[u] = row[t + u * 256]; m = fmaxf(m, v[u]); }
#pragma unroll
    for (int o = 16; o; o >>= 1) m = fmaxf(m, __shfl_xor_sync(~0u, m, o));
    __shared__ float sh[8];
    int wid = t >> 5, lid = t & 31;
    if (lid == 0) sh[wid] = m;
    __syncthreads();
    m = sh[0];
#pragma unroll
    for (int wg = 1; wg < 8; wg++) m = fmaxf(m, sh[wg]);
    __syncthreads();
    float s = 0.f;
#pragma unroll
    for (int u = 0; u < 4; u++) { v[u] = __expf(v[u] - m); s += v[u]; }
#pragma unroll
    for (int o = 16; o; o >>= 1) s += __shfl_xor_sync(~0u, s, o);
    if (lid == 0) sh[wid] = s;
    __syncthreads();
    s = 0.f;
#pragma unroll
    for (int wg = 0; wg < 8; wg++) s += sh[wg];
    float inv = 1.f / s;
#pragma unroll
    for (int u = 0; u < 4; u++) row[t + u * 256] = v[u] * inv;
}

// AV with fused hi/lo split output
__global__ __launch_bounds__(256)
void av_kernel(const float* __restrict__ qkv,
               __nv_bfloat16* __restrict__ oh, __nv_bfloat16* __restrict__ ol) {
    int bh = blockIdx.y;
    int b = bh >> 4, h = bh & 15;
    int qBase = blockIdx.x * 64;
    __shared__ float sA[64][68];
    __shared__ float sV[64][68];
    int tid = threadIdx.x;
    int row = tid >> 2;
    int seg = (tid & 3) * 16;
    int tx = tid & 15, ty = tid >> 4;
    float acc[4][4] = {};
    const float* arow = g_att + ((size_t)bh << 20) + (size_t)(qBase + row) * S + seg;
    const float* vbase = qkv + 2 * D + h * DH;
    for (int kc = 0; kc < S; kc += 64) {
#pragma unroll
        for (int u = 0; u < 4; u++) {
            float4 a4 = *(const float4*)(arow + kc + u * 4);
            *(float4*)&sA[row][seg + u * 4] = a4;
            float4 v4 = *(const float4*)(vbase + (size_t)(b * S + kc + row) * (3 * D) + seg + u * 4);
            *(float4*)&sV[row][seg + u * 4] = v4;
        }
        __syncthreads();
#pragma unroll
        for (int k = 0; k < 64; k++) {
            float ra[4], rv[4];
#pragma unroll
            for (int i = 0; i < 4; i++) ra[i] = sA[ty * 4 + i][k];
#pragma unroll
            for (int j = 0; j < 4; j++) rv[j] = sV[k][tx * 4 + j];
#pragma unroll
            for (int i = 0; i < 4; i++)
#pragma unroll
                for (int j = 0; j < 4; j++)
                    acc[i][j] = fmaf(ra[i], rv[j], acc[i][j]);
        }
        __syncthreads();
    }
#pragma unroll
    for (int i = 0; i < 4; i++)
#pragma unroll
        for (int j = 0; j < 4; j++) {
            size_t o = (size_t)(b * S + qBase + ty * 4 + i) * D + h * DH + tx * 4 + j;
            float v = acc[i][j];
            __nv_bfloat16 hh = __float2bfloat16(v);
            oh[o] = hh;
            ol[o] = __float2bfloat16(v - __bfloat162float(hh));
        }
}

// ---------------- host: launch sequence --------------------------------------
static inline void cvt(const float* x, __nv_bfloat16* hi, __nv_bfloat16* lo, size_t n) {
    int n2 = (int)(n / 2);
    cvt_kernel<<<(n2 + 255) / 256, 256>>>((const float2*)x, (__nv_bfloat162*)hi,
                                          (__nv_bfloat162*)lo, n2);
}

extern "C" void kernel_launch(void* const* d_in, const int* in_sizes, int n_in,
                              void* d_out, int out_size) {
    const int*   idx    = (const int*)  d_in[0];
    const float* vis    = (const float*)d_in[1];
    const float* wte    = (const float*)d_in[2];
    const float* wpe    = (const float*)d_in[3];
    const float* qkv_w  = (const float*)d_in[4];
    const float* qkv_b  = (const float*)d_in[5];
    const float* out_w  = (const float*)d_in[6];
    const float* out_b  = (const float*)d_in[7];
    const float* ln1_w  = (const float*)d_in[8];
    const float* ln1_b  = (const float*)d_in[9];
    const float* ln2_w  = (const float*)d_in[10];
    const float* ln2_b  = (const float*)d_in[11];
    const float* ff1_w  = (const float*)d_in[12];
    const float* ff1_b  = (const float*)d_in[13];
    const float* ff2_w  = (const float*)d_in[14];
    const float* ff2_b  = (const float*)d_in[15];
    const float* lnf_w  = (const float*)d_in[16];
    const float* lnf_b  = (const float*)d_in[17];
    float* logits = (float*)d_out;

    cudaFuncSetAttribute(gemm_mma<true,  false, false, false>, cudaFuncAttributeMaxDynamicSharedMemorySize, GEMM_SMEM);
    cudaFuncSetAttribute(gemm_mma<true,  false, true,  false>, cudaFuncAttributeMaxDynamicSharedMemorySize, GEMM_SMEM);
    cudaFuncSetAttribute(gemm_mma<true,  true,  false, true >, cudaFuncAttributeMaxDynamicSharedMemorySize, GEMM_SMEM);
    cudaFuncSetAttribute(gemm_mma<false, false, false, false>, cudaFuncAttributeMaxDynamicSharedMemorySize, GEMM_SMEM);

    float *px, *pqkv;
    cudaGetSymbolAddress((void**)&px,   g_x);
    cudaGetSymbolAddress((void**)&pqkv, g_qkv);
    __nv_bfloat16 *pah, *pal, *pa2h, *pa2l, *pwqh, *pwql, *pwoh, *pwol, *pf1h, *pf1l, *pf2h, *pf2l, *pteh, *ptel;
    cudaGetSymbolAddress((void**)&pah,  a_h);
    cudaGetSymbolAddress((void**)&pal,  a_l);
    cudaGetSymbolAddress((void**)&pa2h, a2_h);
    cudaGetSymbolAddress((void**)&pa2l, a2_l);
    cudaGetSymbolAddress((void**)&pwqh, w_qkv_h);
    cudaGetSymbolAddress((void**)&pwql, w_qkv_l);
    cudaGetSymbolAddress((void**)&pwoh, w_out_h);
    cudaGetSymbolAddress((void**)&pwol, w_out_l);
    cudaGetSymbolAddress((void**)&pf1h, w_ff1_h);
    cudaGetSymbolAddress((void**)&pf1l, w_ff1_l);
    cudaGetSymbolAddress((void**)&pf2h, w_ff2_h);
    cudaGetSymbolAddress((void**)&pf2l, w_ff2_l);
    cudaGetSymbolAddress((void**)&pteh, w_te_h);
    cudaGetSymbolAddress((void**)&ptel, w_te_l);

    // weight conversions (fp32 -> bf16 hi/lo) — must run every call (determinism)
    cvt(qkv_w, pwqh, pwql, (size_t)L * 3 * D * D);
    cvt(out_w, pwoh, pwol, (size_t)L * D * D);
    cvt(ff1_w, pf1h, pf1l, (size_t)L * 4 * D * D);
    cvt(ff2_w, pf2h, pf2l, (size_t)L * 4 * D * D);
    cvt(wte,   pteh, ptel, (size_t)V * D);

    pe_kernel<<<1, 32>>>(idx);
    embed_kernel<<<(NTOK * D) / 256, 256>>>(idx, vis, wte, wpe);

    for (int l = 0; l < L; l++) {
        const __nv_bfloat16* qwh = pwqh + (size_t)l * 3 * D * D;
        const __nv_bfloat16* qwl = pwql + (size_t)l * 3 * D * D;
        const __nv_bfloat16* owh = pwoh + (size_t)l * D * D;
        const __nv_bfloat16* owl = pwol + (size_t)l * D * D;
        const __nv_bfloat16* f1h = pf1h + (size_t)l * 4 * D * D;
        const __nv_bfloat16* f1l = pf1l + (size_t)l * 4 * D * D;
        const __nv_bfloat16* f2h = pf2h + (size_t)l * 4 * D * D;
        const __nv_bfloat16* f2l = pf2l + (size_t)l * 4 * D * D;
        const float* qb  = qkv_b + (size_t)l * 3 * D;
        const float* ob  = out_b + (size_t)l * D;
        const float* f1b = ff1_b + (size_t)l * 4 * D;
        const float* f2b = ff2_b + (size_t)l * D;

        ln_split_kernel<<<NTOK, 256>>>(px, ln1_w + l * D, ln1_b + l * D, pah, pal);
        gemm_mma<true, false, false, false><<<dim3(NTOK / 128, 3 * D / 128), 256, GEMM_SMEM>>>(
            pah, pal, qwh, qwl, qb, nullptr, pqkv, nullptr, nullptr, 3 * D, D);

        scores_kernel<<<dim3(S / 64, S / 64, B * H), 256>>>(pqkv);
        softmax_kernel<<<B * H * S, 256>>>();
        av_kernel<<<dim3(S / 64, B * H), 256>>>(pqkv, pah, pal);

        gemm_mma<true, false, true, false><<<dim3(NTOK / 128, D / 128), 256, GEMM_SMEM>>>(
            pah, pal, owh, owl, ob, px, px, nullptr, nullptr, D, D);

        ln_split_kernel<<<NTOK, 256>>>(px, ln2_w + l * D, ln2_b + l * D, pah, pal);
        gemm_mma<true, true, false, true><<<dim3(NTOK / 128, 4 * D / 128), 256, GEMM_SMEM>>>(
            pah, pal, f1h, f1l, f1b, nullptr, nullptr, pa2h, pa2l, 4 * D, D);

        gemm_mma<true, false, true, false><<<dim3(NTOK / 128, D / 128), 256, GEMM_SMEM>>>(
            pa2h, pa2l, f2h, f2l, f2b, px, px, nullptr, nullptr, D, 4 * D);
    }

    ln_split_kernel<<<NTOK, 256>>>(px, lnf_w, lnf_b, pah, pal);
    gemm_mma<false, false, false, false><<<dim3(NTOK / 128, V / 128), 256, GEMM_SMEM>>>(
        pah, pal, pteh, ptel, nullptr, nullptr, logits, nullptr, nullptr, V, D);
}

// round 7
// speedup vs baseline: 2.5671x; 1.2781x over previous
#include <cuda_runtime.h>
#include <cuda_bf16.h>
#include <math.h>
#include <stdint.h>
#include <stddef.h>

// Problem constants
constexpr int B   = 2;
constexpr int T   = 768;
constexpr int KV  = 256;
constexpr int S   = 1024;
constexpr int D   = 1024;
constexpr int H   = 16;
constexpr int DH  = 64;
constexpr int L   = 6;
constexpr int V   = 32000;
constexpr int NTOK = B * S;
constexpr int PHYS_TOK = 5;

// ---------------- fp32 scratch ----------------------------------------------
__device__ float g_x  [NTOK * D];
__device__ float g_qkv[NTOK * 3 * D];
__device__ int   g_pe [B];

// ---------------- bf16 split (hi/lo) storage --------------------------------
__device__ __nv_bfloat16 w_qkv_h[L*3*D*D], w_qkv_l[L*3*D*D];
__device__ __nv_bfloat16 w_out_h[L*D*D],   w_out_l[L*D*D];
__device__ __nv_bfloat16 w_ff1_h[L*4*D*D], w_ff1_l[L*4*D*D];
__device__ __nv_bfloat16 w_ff2_h[L*4*D*D], w_ff2_l[L*4*D*D];
__device__ __nv_bfloat16 w_te_h [(size_t)V*D], w_te_l[(size_t)V*D];
__device__ __nv_bfloat16 a_h [NTOK*D],     a_l [NTOK*D];     // activations [NTOK,D]
__device__ __nv_bfloat16 a2_h[NTOK*4*D],   a2_l[NTOK*4*D];   // FF hidden   [NTOK,4D]

// ============================ PTX helpers ====================================
__device__ __forceinline__ uint32_t smem_to_u32(const void* p) {
    uint32_t a;
    asm("{ .reg .u64 t; cvta.to.shared.u64 t, %1; cvt.u32.u64 %0, t; }" : "=r"(a) : "l"(p));
    return a;
}
__device__ __forceinline__ void ldmx4(uint32_t* r, uint32_t addr) {
    asm volatile("ldmatrix.sync.aligned.m8n8.x4.shared.b16 {%0,%1,%2,%3}, [%4];"
        : "=r"(r[0]), "=r"(r[1]), "=r"(r[2]), "=r"(r[3]) : "r"(addr));
}
__device__ __forceinline__ void ldmx4t(uint32_t* r, uint32_t addr) {
    asm volatile("ldmatrix.sync.aligned.m8n8.x4.trans.shared.b16 {%0,%1,%2,%3}, [%4];"
        : "=r"(r[0]), "=r"(r[1]), "=r"(r[2]), "=r"(r[3]) : "r"(addr));
}
__device__ __forceinline__ void mma16816(float* c, const uint32_t* a, const uint32_t* b) {
    asm volatile("mma.sync.aligned.m16n8k16.row.col.f32.bf16.bf16.f32 "
        "{%0,%1,%2,%3}, {%4,%5,%6,%7}, {%8,%9}, {%0,%1,%2,%3};"
        : "+f"(c[0]), "+f"(c[1]), "+f"(c[2]), "+f"(c[3])
        : "r"(a[0]), "r"(a[1]), "r"(a[2]), "r"(a[3]), "r"(b[0]), "r"(b[1]));
}
__device__ __forceinline__ void cp16(uint32_t dst, const void* src) {
    asm volatile("cp.async.cg.shared.global [%0], [%1], 16;" :: "r"(dst), "l"(src));
}
__device__ __forceinline__ void cp_commit() {
    asm volatile("cp.async.commit_group;" ::: "memory");
}
template<int N>
__device__ __forceinline__ void cp_wait() {
    asm volatile("cp.async.wait_group %0;" :: "n"(N) : "memory");
}
__device__ __forceinline__ uint32_t pack_bf2(float a, float b) {
    __nv_bfloat162 t;
    t.x = __float2bfloat16(a); t.y = __float2bfloat16(b);
    return *(uint32_t*)&t;
}

// ---------------- small kernels ----------------------------------------------
__global__ void pe_kernel(const int* __restrict__ idx) {
    int b = threadIdx.x;
    if (b < B) {
        int pe = 0;
        for (int s = 0; s < T; s++)
            if (idx[b * T + s] == PHYS_TOK) { pe = s + 1; break; }
        g_pe[b] = pe;
    }
}

__global__ void embed_kernel(const int* __restrict__ idx, const float* __restrict__ vis,
                             const float* __restrict__ wte, const float* __restrict__ wpe) {
    int i = blockIdx.x * blockDim.x + threadIdx.x;
    int d = i & (D - 1);
    int p = (i / D) & (S - 1);
    int b = i / (D * S);
    int pe = g_pe[b];
    float v;
    if (p >= pe && p < pe + KV) {
        v = vis[((size_t)b * KV + (p - pe)) * D + d];
    } else {
        int ti = (p < pe) ? p : (p - KV);
        ti = min(max(ti, 0), T - 1);
        v = wte[(size_t)idx[b * T + ti] * D + d];
    }
    g_x[i] = v + wpe[(size_t)p * D + d];
}

// LayerNorm with fused hi/lo split output
__global__ void ln_split_kernel(const float* __restrict__ in,
                                const float* __restrict__ w, const float* __restrict__ b,
                                __nv_bfloat16* __restrict__ oh, __nv_bfloat16* __restrict__ ol) {
    int row = blockIdx.x;
    const float* x = in + (size_t)row * D;
    float v[4]; float s = 0.f, s2 = 0.f;
#pragma unroll
    for (int u = 0; u < 4; u++) { v[u] = x[threadIdx.x + u * 256]; s += v[u]; s2 += v[u] * v[u]; }
#pragma unroll
    for (int o = 16; o; o >>= 1) { s += __shfl_xor_sync(~0u, s, o); s2 += __shfl_xor_sync(~0u, s2, o); }
    __shared__ float sh1[8], sh2[8];
    int wid = threadIdx.x >> 5, lid = threadIdx.x & 31;
    if (lid == 0) { sh1[wid] = s; sh2[wid] = s2; }
    __syncthreads();
    s = 0.f; s2 = 0.f;
#pragma unroll
    for (int wg = 0; wg < 8; wg++) { s += sh1[wg]; s2 += sh2[wg]; }
    float mean = s * (1.f / D);
    float var  = s2 * (1.f / D) - mean * mean;
    float inv  = rsqrtf(var + 1e-5f);
#pragma unroll
    for (int u = 0; u < 4; u++) {
        int j = threadIdx.x + u * 256;
        float y = (v[u] - mean) * inv * w[j] + b[j];
        __nv_bfloat16 h = __float2bfloat16(y);
        oh[(size_t)row * D + j] = h;
        ol[(size_t)row * D + j] = __float2bfloat16(y - __bfloat162float(h));
    }
}

// fp32 -> bf16 hi/lo split (weights)
__global__ void cvt_kernel(const float2* __restrict__ x, __nv_bfloat162* __restrict__ hi,
                           __nv_bfloat162* __restrict__ lo, int n2) {
    int i = blockIdx.x * blockDim.x + threadIdx.x;
    if (i >= n2) return;
    float2 v = x[i];
    __nv_bfloat162 h;
    h.x = __float2bfloat16(v.x);
    h.y = __float2bfloat16(v.y);
    float2 hf = make_float2(__bfloat162float(h.x), __bfloat162float(h.y));
    __nv_bfloat162 l;
    l.x = __float2bfloat16(v.x - hf.x);
    l.y = __float2bfloat16(v.y - hf.y);
    hi[i] = h; lo[i] = l;
}

__device__ __forceinline__ float gelu_exact(float x) {
    return 0.5f * x * (1.f + erff(x * 0.70710678118654752f));
}

// ================= mma.sync split-bf16 GEMM, cp.async double-buffered ========
constexpr int LDSROW = 40;                    // 32 + 8 pad (bf16 elems)
constexpr int TILE_BYTES = 128 * LDSROW * 2;  // 10240
constexpr int BUF_BYTES  = 4 * TILE_BYTES;    // 40960
constexpr int GEMM_SMEM  = 2 * BUF_BYTES;     // 81920

__device__ __forceinline__ void cp_tile(uint32_t dst, const __nv_bfloat16* __restrict__ src,
                                        int Kd, int k0) {
    int tid = threadIdx.x;
#pragma unroll
    for (int i = 0; i < 2; i++) {
        int v = tid * 2 + i;
        int row = v >> 2, seg = v & 3;
        cp16(dst + (uint32_t)(row * LDSROW + seg * 8) * 2,
             src + (size_t)row * Kd + k0 + seg * 8);
    }
}

template<bool BIAS, bool GELU, bool RES, bool SPLIT>
__global__ __launch_bounds__(256, 2)
void gemm_mma(const __nv_bfloat16* __restrict__ Ah, const __nv_bfloat16* __restrict__ Al,
              const __nv_bfloat16* __restrict__ Wh, const __nv_bfloat16* __restrict__ Wl,
              const float* __restrict__ bias, const float* __restrict__ res,
              float* __restrict__ C, __nv_bfloat16* __restrict__ Ch,
              __nv_bfloat16* __restrict__ Cl, int N, int Kd) {
    extern __shared__ char smem[];
    const uint32_t sbase = smem_to_u32(smem);

    const int tid  = threadIdx.x;
    const int lane = tid & 31;
    const int wid  = tid >> 5;
    const int wm   = wid >> 1;
    const int wn   = wid & 1;
    const int bm   = blockIdx.x * 128;
    const int bn   = blockIdx.y * 128;

    const __nv_bfloat16* A0h = Ah + (size_t)bm * Kd;
    const __nv_bfloat16* A0l = Al + (size_t)bm * Kd;
    const __nv_bfloat16* W0h = Wh + (size_t)bn * Kd;
    const __nv_bfloat16* W0l = Wl + (size_t)bn * Kd;

    const uint32_t frag_lane = (uint32_t)((lane & 15) * LDSROW + (lane >> 4) * 8);
    const int nch = Kd / 32;

    auto issue = [&](int ch) {
        uint32_t b = sbase + (uint32_t)(ch & 1) * BUF_BYTES;
        int k0 = ch * 32;
        cp_tile(b,                  A0h, Kd, k0);
        cp_tile(b + TILE_BYTES,     A0l, Kd, k0);
        cp_tile(b + 2 * TILE_BYTES, W0h, Kd, k0);
        cp_tile(b + 3 * TILE_BYTES, W0l, Kd, k0);
        cp_commit();
    };

    float c[2][8][4];
#pragma unroll
    for (int mt = 0; mt < 2; mt++)
#pragma unroll
        for (int nt = 0; nt < 8; nt++)
#pragma unroll
            for (int q = 0; q < 4; q++) c[mt][nt][q] = 0.f;

    issue(0);
    if (nch > 1) issue(1);

    for (int ch = 0; ch < nch; ch++) {
        if (ch < nch - 1) cp_wait<1>(); else cp_wait<0>();
        __syncthreads();
        uint32_t b = sbase + (uint32_t)(ch & 1) * BUF_BYTES;
#pragma unroll
        for (int ks = 0; ks < 2; ks++) {
            uint32_t ah[2][4], al[2][4];
#pragma unroll
            for (int mt = 0; mt < 2; mt++) {
                uint32_t off = ((uint32_t)((wm * 32 + mt * 16) * LDSROW + ks * 16) + frag_lane) * 2;
                ldmx4(ah[mt], b + off);
                ldmx4(al[mt], b + TILE_BYTES + off);
            }
#pragma unroll
            for (int jj = 0; jj < 4; jj++) {
                uint32_t off = ((uint32_t)((wn * 64 + jj * 16) * LDSROW + ks * 16) + frag_lane) * 2;
                uint32_t th[4], tl[4];
                ldmx4(th, b + 2 * TILE_BYTES + off);
                ldmx4(tl, b + 3 * TILE_BYTES + off);
                uint32_t bh0[2] = { th[0], th[2] }, bh1[2] = { th[1], th[3] };
                uint32_t bl0[2] = { tl[0], tl[2] }, bl1[2] = { tl[1], tl[3] };
#pragma unroll
                for (int mt = 0; mt < 2; mt++) {
                    mma16816(c[mt][jj * 2],     ah[mt], bh0);
                    mma16816(c[mt][jj * 2],     ah[mt], bl0);
                    mma16816(c[mt][jj * 2],     al[mt], bh0);
                    mma16816(c[mt][jj * 2 + 1], ah[mt], bh1);
                    mma16816(c[mt][jj * 2 + 1], ah[mt], bl1);
                    mma16816(c[mt][jj * 2 + 1], al[mt], bh1);
                }
            }
        }
        __syncthreads();
        if (ch + 2 < nch) issue(ch + 2);
    }

    const int row0 = bm + wm * 32;
    const int col0 = bn + wn * 64;
#pragma unroll
    for (int mt = 0; mt < 2; mt++) {
#pragma unroll
        for (int nt = 0; nt < 8; nt++) {
            int r  = row0 + mt * 16 + (lane >> 2);
            int cl = col0 + nt * 8 + (lane & 3) * 2;
#pragma unroll
            for (int half = 0; half < 2; half++) {
                int rr = r + half * 8;
                float v0 = c[mt][nt][half * 2];
                float v1 = c[mt][nt][half * 2 + 1];
                if (BIAS) { v0 += bias[cl]; v1 += bias[cl + 1]; }
                if (GELU) { v0 = gelu_exact(v0); v1 = gelu_exact(v1); }
                if (RES) {
                    const float* rp = res + (size_t)rr * N + cl;
                    v0 += rp[0]; v1 += rp[1];
                }
                if (SPLIT) {
                    __nv_bfloat162 hh, ll;
                    hh.x = __float2bfloat16(v0);
                    hh.y = __float2bfloat16(v1);
                    ll.x = __float2bfloat16(v0 - __bfloat162float(hh.x));
                    ll.y = __float2bfloat16(v1 - __bfloat162float(hh.y));
                    *(__nv_bfloat162*)(Ch + (size_t)rr * N + cl) = hh;
                    *(__nv_bfloat162*)(Cl + (size_t)rr * N + cl) = ll;
                } else {
                    *(float2*)(C + (size_t)rr * N + cl) = make_float2(v0, v1);
                }
            }
        }
    }
}

// ================= fused flash attention (split-bf16 mma) ====================
// grid (S/128, B*H), 256 threads (8 warps x 16 q-rows). K-tile = 64 keys.
constexpr int QROW = 72;   // 64 + 8 pad
constexpr int FLASH_SMEM = (128 * QROW * 2 + 4 * 64 * QROW) * 2; // Qh,Ql + Kh,Kl,Vh,Vl

__global__ __launch_bounds__(256, 1)
void flash_kernel(const float* __restrict__ qkv,
                  __nv_bfloat16* __restrict__ oh, __nv_bfloat16* __restrict__ ol) {
    extern __shared__ char smem[];
    __nv_bfloat16* sQh = (__nv_bfloat16*)smem;
    __nv_bfloat16* sQl = sQh + 128 * QROW;
    __nv_bfloat16* sKh = sQl + 128 * QROW;
    __nv_bfloat16* sKl = sKh + 64 * QROW;
    __nv_bfloat16* sVh = sKl + 64 * QROW;
    __nv_bfloat16* sVl = sVh + 64 * QROW;

    const int tid = threadIdx.x, lane = tid & 31, w = tid >> 5;
    const int bh = blockIdx.y, b = bh >> 4, h = bh & 15;
    const int qBase = blockIdx.x * 128;
    const int pe = g_pe[b], ve = pe + KV;

    // ---- load Q tile (fp32 -> split bf16 smem) ----
    for (int i = tid; i < 2048; i += 256) {
        int row = i >> 4, col = (i & 15) * 4;
        float4 q4 = *(const float4*)(qkv + (size_t)(b * S + qBase + row) * (3 * D) + h * DH + col);
        int o = row * QROW + col;
        float f[4] = { q4.x, q4.y, q4.z, q4.w };
#pragma unroll
        for (int u = 0; u < 4; u++) {
            __nv_bfloat16 hh = __float2bfloat16(f[u]);
            sQh[o + u] = hh;
            sQl[o + u] = __float2bfloat16(f[u] - __bfloat162float(hh));
        }
    }
    __syncthreads();

    // ---- Q fragments to registers ----
    const uint32_t aQh = smem_to_u32(sQh), aQl = smem_to_u32(sQl);
    const uint32_t aKh = smem_to_u32(sKh), aKl = smem_to_u32(sKl);
    const uint32_t aVh = smem_to_u32(sVh), aVl = smem_to_u32(sVl);
    const uint32_t flq = (uint32_t)((lane & 15) * QROW + (lane >> 4) * 8);
    uint32_t qh[4][4], ql[4][4];
#pragma unroll
    for (int kk = 0; kk < 4; kk++) {
        uint32_t off = ((uint32_t)(w * 16 * QROW + kk * 16) + flq) * 2;
        ldmx4(qh[kk], aQh + off);
        ldmx4(ql[kk], aQl + off);
    }

    float acc[8][4];
#pragma unroll
    for (int nt = 0; nt < 8; nt++)
#pragma unroll
        for (int e = 0; e < 4; e++) acc[nt][e] = 0.f;
    float m0 = -1e30f, m1 = -1e30f, l0 = 0.f, l1 = 0.f;

    const int qr = qBase + w * 16 + (lane >> 2);
    const int kEnd = min(S, max(qBase + 128, ve));

    for (int k0 = 0; k0 < kEnd; k0 += 64) {
        __syncthreads();   // previous iteration's ldmatrix reads done
        // ---- load K,V tile (fp32 -> split bf16 smem) ----
        for (int i = tid; i < 1024; i += 256) {
            int row = i >> 4, col = (i & 15) * 4;
            const float* base = qkv + (size_t)(b * S + k0 + row) * (3 * D) + h * DH + col;
            float4 k4 = *(const float4*)(base + D);
            float4 v4 = *(const float4*)(base + 2 * D);
            int o = row * QROW + col;
            float fk[4] = { k4.x, k4.y, k4.z, k4.w };
            float fv[4] = { v4.x, v4.y, v4.z, v4.w };
#pragma unroll
            for (int u = 0; u < 4; u++) {
                __nv_bfloat16 hk = __float2bfloat16(fk[u]);
                sKh[o + u] = hk;
                sKl[o + u] = __float2bfloat16(fk[u] - __bfloat162float(hk));
                __nv_bfloat16 hv = __float2bfloat16(fv[u]);
                sVh[o + u] = hv;
                sVl[o + u] = __float2bfloat16(fv[u] - __bfloat162float(hv));
            }
        }
        __syncthreads();

        // ---- S = Q K^T (split 3-term) ----
        float c[8][4];
#pragma unroll
        for (int nt = 0; nt < 8; nt++)
#pragma unroll
            for (int e = 0; e < 4; e++) c[nt][e] = 0.f;
#pragma unroll
        for (int kk = 0; kk < 4; kk++) {
#pragma unroll
            for (int jj = 0; jj < 4; jj++) {
                uint32_t off = ((uint32_t)((jj * 16) * QROW + kk * 16) + flq) * 2;
                uint32_t th[4], tl[4];
                ldmx4(th, aKh + off);
                ldmx4(tl, aKl + off);
                uint32_t bh0[2] = { th[0], th[2] }, bh1[2] = { th[1], th[3] };
                uint32_t bl0[2] = { tl[0], tl[2] }, bl1[2] = { tl[1], tl[3] };
                mma16816(c[jj * 2],     qh[kk], bh0);
                mma16816(c[jj * 2],     qh[kk], bl0);
                mma16816(c[jj * 2],     ql[kk], bh0);
                mma16816(c[jj * 2 + 1], qh[kk], bh1);
                mma16816(c[jj * 2 + 1], qh[kk], bl1);
                mma16816(c[jj * 2 + 1], ql[kk], bh1);
            }
        }

        // ---- mask + scale + tile row-max ----
        float mx0 = -1e30f, mx1 = -1e30f;
#pragma unroll
        for (int nt = 0; nt < 8; nt++) {
            int kc = k0 + nt * 8 + (lane & 3) * 2;
#pragma unroll
            for (int e = 0; e < 4; e++) {
                int q = qr + ((e >= 2) ? 8 : 0);
                int k = kc + (e & 1);
                bool allowed = (q < pe && k < pe) ||
                               (q >= pe && q < ve && k < ve) ||
                               (q >= ve && k <= q);
                float s = allowed ? c[nt][e] * 0.125f : -1e9f;
                c[nt][e] = s;
                if (e < 2) mx0 = fmaxf(mx0, s); else mx1 = fmaxf(mx1, s);
            }
        }
        mx0 = fmaxf(mx0, __shfl_xor_sync(~0u, mx0, 1));
        mx0 = fmaxf(mx0, __shfl_xor_sync(~0u, mx0, 2));
        mx1 = fmaxf(mx1, __shfl_xor_sync(~0u, mx1, 1));
        mx1 = fmaxf(mx1, __shfl_xor_sync(~0u, mx1, 2));

        float mn0 = fmaxf(m0, mx0), mn1 = fmaxf(m1, mx1);
        float al0 = __expf(m0 - mn0), al1 = __expf(m1 - mn1);
        m0 = mn0; m1 = mn1;

        // ---- P = exp(S - m), pack as split A-fragments ----
        uint32_t ph[4][4], pl[4][4];
        float rs0 = 0.f, rs1 = 0.f;
#pragma unroll
        for (int nt = 0; nt < 8; nt++) {
            float p0 = __expf(c[nt][0] - m0);
            float p1 = __expf(c[nt][1] - m0);
            float p2 = __expf(c[nt][2] - m1);
            float p3 = __expf(c[nt][3] - m1);
            rs0 += p0 + p1; rs1 += p2 + p3;
            __nv_bfloat16 h0 = __float2bfloat16(p0), h1 = __float2bfloat16(p1);
            __nv_bfloat16 h2 = __float2bfloat16(p2), h3 = __float2bfloat16(p3);
            int ck = nt >> 1, ps = (nt & 1) * 2;
            __nv_bfloat162 t;
            t.x = h0; t.y = h1; ph[ck][ps]     = *(uint32_t*)&t;
            t.x = h2; t.y = h3; ph[ck][ps + 1] = *(uint32_t*)&t;
            pl[ck][ps]     = pack_bf2(p0 - __bfloat162float(h0), p1 - __bfloat162float(h1));
            pl[ck][ps + 1] = pack_bf2(p2 - __bfloat162float(h2), p3 - __bfloat162float(h3));
        }
        rs0 += __shfl_xor_sync(~0u, rs0, 1); rs0 += __shfl_xor_sync(~0u, rs0, 2);
        rs1 += __shfl_xor_sync(~0u, rs1, 1); rs1 += __shfl_xor_sync(~0u, rs1, 2);
        l0 = l0 * al0 + rs0;
        l1 = l1 * al1 + rs1;

        // ---- rescale O ----
#pragma unroll
        for (int nt = 0; nt < 8; nt++) {
            acc[nt][0] *= al0; acc[nt][1] *= al0;
            acc[nt][2] *= al1; acc[nt][3] *= al1;
        }

        // ---- O += P V (split 3-term), V via ldmatrix.trans ----
        const uint32_t flv = (uint32_t)(((lane & 7) + ((lane >> 3) & 1) * 8) * QROW + (lane >> 4) * 8);
#pragma unroll
        for (int kk = 0; kk < 4; kk++) {
#pragma unroll
            for (int jj = 0; jj < 4; jj++) {
                uint32_t off = ((uint32_t)(kk * 16 * QROW + jj * 16) + flv) * 2;
                uint32_t th[4], tl[4];
                ldmx4t(th, aVh + off);
                ldmx4t(tl, aVl + off);
                uint32_t bh0[2] = { th[0], th[1] }, bh1[2] = { th[2], th[3] };
                uint32_t bl0[2] = { tl[0], tl[1] }, bl1[2] = { tl[2], tl[3] };
                mma16816(acc[jj * 2],     ph[kk], bh0);
                mma16816(acc[jj * 2],     ph[kk], bl0);
                mma16816(acc[jj * 2],     pl[kk], bh0);
                mma16816(acc[jj * 2 + 1], ph[kk], bh1);
                mma16816(acc[jj * 2 + 1], ph[kk], bl1);
                mma16816(acc[jj * 2 + 1], pl[kk], bh1);
            }
        }
    }

    // ---- normalize + split write ----
    const float il0 = 1.f / l0, il1 = 1.f / l1;
#pragma unroll
    for (int nt = 0; nt < 8; nt++) {
        int dcol = h * DH + nt * 8 + (lane & 3) * 2;
        size_t o0 = (size_t)(b * S + qr) * D + dcol;
        size_t o1 = (size_t)(b * S + qr + 8) * D + dcol;
        float v0 = acc[nt][0] * il0, v1 = acc[nt][1] * il0;
        float v2 = acc[nt][2] * il1, v3 = acc[nt][3] * il1;
        __nv_bfloat162 hh, ll;
        hh.x = __float2bfloat16(v0); hh.y = __float2bfloat16(v1);
        ll.x = __float2bfloat16(v0 - __bfloat162float(hh.x));
        ll.y = __float2bfloat16(v1 - __bfloat162float(hh.y));
        *(__nv_bfloat162*)(oh + o0) = hh;
        *(__nv_bfloat162*)(ol + o0) = ll;
        hh.x = __float2bfloat16(v2); hh.y = __float2bfloat16(v3);
        ll.x = __float2bfloat16(v2 - __bfloat162float(hh.x));
        ll.y = __float2bfloat16(v3 - __bfloat162float(hh.y));
        *(__nv_bfloat162*)(oh + o1) = hh;
        *(__nv_bfloat162*)(ol + o1) = ll;
    }
}

// ---------------- host: launch sequence --------------------------------------
static inline void cvt(const float* x, __nv_bfloat16* hi, __nv_bfloat16* lo, size_t n) {
    int n2 = (int)(n / 2);
    cvt_kernel<<<(n2 + 255) / 256, 256>>>((const float2*)x, (__nv_bfloat162*)hi,
                                          (__nv_bfloat162*)lo, n2);
}

extern "C" void kernel_launch(void* const* d_in, const int* in_sizes, int n_in,
                              void* d_out, int out_size) {
    const int*   idx    = (const int*)  d_in[0];
    const float* vis    = (const float*)d_in[1];
    const float* wte    = (const float*)d_in[2];
    const float* wpe    = (const float*)d_in[3];
    const float* qkv_w  = (const float*)d_in[4];
    const float* qkv_b  = (const float*)d_in[5];
    const float* out_w  = (const float*)d_in[6];
    const float* out_b  = (const float*)d_in[7];
    const float* ln1_w  = (const float*)d_in[8];
    const float* ln1_b  = (const float*)d_in[9];
    const float* ln2_w  = (const float*)d_in[10];
    const float* ln2_b  = (const float*)d_in[11];
    const float* ff1_w  = (const float*)d_in[12];
    const float* ff1_b  = (const float*)d_in[13];
    const float* ff2_w  = (const float*)d_in[14];
    const float* ff2_b  = (const float*)d_in[15];
    const float* lnf_w  = (const float*)d_in[16];
    const float* lnf_b  = (const float*)d_in[17];
    float* logits = (float*)d_out;

    cudaFuncSetAttribute(gemm_mma<true,  false, false, false>, cudaFuncAttributeMaxDynamicSharedMemorySize, GEMM_SMEM);
    cudaFuncSetAttribute(gemm_mma<true,  false, true,  false>, cudaFuncAttributeMaxDynamicSharedMemorySize, GEMM_SMEM);
    cudaFuncSetAttribute(gemm_mma<true,  true,  false, true >, cudaFuncAttributeMaxDynamicSharedMemorySize, GEMM_SMEM);
    cudaFuncSetAttribute(gemm_mma<false, false, false, false>, cudaFuncAttributeMaxDynamicSharedMemorySize, GEMM_SMEM);
    cudaFuncSetAttribute(flash_kernel, cudaFuncAttributeMaxDynamicSharedMemorySize, FLASH_SMEM);

    float *px, *pqkv;
    cudaGetSymbolAddress((void**)&px,   g_x);
    cudaGetSymbolAddress((void**)&pqkv, g_qkv);
    __nv_bfloat16 *pah, *pal, *pa2h, *pa2l, *pwqh, *pwql, *pwoh, *pwol, *pf1h, *pf1l, *pf2h, *pf2l, *pteh, *ptel;
    cudaGetSymbolAddress((void**)&pah,  a_h);
    cudaGetSymbolAddress((void**)&pal,  a_l);
    cudaGetSymbolAddress((void**)&pa2h, a2_h);
    cudaGetSymbolAddress((void**)&pa2l, a2_l);
    cudaGetSymbolAddress((void**)&pwqh, w_qkv_h);
    cudaGetSymbolAddress((void**)&pwql, w_qkv_l);
    cudaGetSymbolAddress((void**)&pwoh, w_out_h);
    cudaGetSymbolAddress((void**)&pwol, w_out_l);
    cudaGetSymbolAddress((void**)&pf1h, w_ff1_h);
    cudaGetSymbolAddress((void**)&pf1l, w_ff1_l);
    cudaGetSymbolAddress((void**)&pf2h, w_ff2_h);
    cudaGetSymbolAddress((void**)&pf2l, w_ff2_l);
    cudaGetSymbolAddress((void**)&pteh, w_te_h);
    cudaGetSymbolAddress((void**)&ptel, w_te_l);

    // weight conversions (fp32 -> bf16 hi/lo) — must run every call (determinism)
    cvt(qkv_w, pwqh, pwql, (size_t)L * 3 * D * D);
    cvt(out_w, pwoh, pwol, (size_t)L * D * D);
    cvt(ff1_w, pf1h, pf1l, (size_t)L * 4 * D * D);
    cvt(ff2_w, pf2h, pf2l, (size_t)L * 4 * D * D);
    cvt(wte,   pteh, ptel, (size_t)V * D);

    pe_kernel<<<1, 32>>>(idx);
    embed_kernel<<<(NTOK * D) / 256, 256>>>(idx, vis, wte, wpe);

    for (int l = 0; l < L; l++) {
        const __nv_bfloat16* qwh = pwqh + (size_t)l * 3 * D * D;
        const __nv_bfloat16* qwl = pwql + (size_t)l * 3 * D * D;
        const __nv_bfloat16* owh = pwoh + (size_t)l * D * D;
        const __nv_bfloat16* owl = pwol + (size_t)l * D * D;
        const __nv_bfloat16* f1h = pf1h + (size_t)l * 4 * D * D;
        const __nv_bfloat16* f1l = pf1l + (size_t)l * 4 * D * D;
        const __nv_bfloat16* f2h = pf2h + (size_t)l * 4 * D * D;
        const __nv_bfloat16* f2l = pf2l + (size_t)l * 4 * D * D;
        const float* qb  = qkv_b + (size_t)l * 3 * D;
        const float* ob  = out_b + (size_t)l * D;
        const float* f1b = ff1_b + (size_t)l * 4 * D;
        const float* f2b = ff2_b + (size_t)l * D;

        ln_split_kernel<<<NTOK, 256>>>(px, ln1_w + l * D, ln1_b + l * D, pah, pal);
        gemm_mma<true, false, false, false><<<dim3(NTOK / 128, 3 * D / 128), 256, GEMM_SMEM>>>(
            pah, pal, qwh, qwl, qb, nullptr, pqkv, nullptr, nullptr, 3 * D, D);

        flash_kernel<<<dim3(S / 128, B * H), 256, FLASH_SMEM>>>(pqkv, pah, pal);

        gemm_mma<true, false, true, false><<<dim3(NTOK / 128, D / 128), 256, GEMM_SMEM>>>(
            pah, pal, owh, owl, ob, px, px, nullptr, nullptr, D, D);

        ln_split_kernel<<<NTOK, 256>>>(px, ln2_w + l * D, ln2_b + l * D, pah, pal);
        gemm_mma<true, true, false, true><<<dim3(NTOK / 128, 4 * D / 128), 256, GEMM_SMEM>>>(
            pah, pal, f1h, f1l, f1b, nullptr, nullptr, pa2h, pa2l, 4 * D, D);

        gemm_mma<true, false, true, false><<<dim3(NTOK / 128, D / 128), 256, GEMM_SMEM>>>(
            pa2h, pa2l, f2h, f2l, f2b, px, px, nullptr, nullptr, D, 4 * D);
    }

    ln_split_kernel<<<NTOK, 256>>>(px, lnf_w, lnf_b, pah, pal);
    gemm_mma<false, false, false, false><<<dim3(NTOK / 128, V / 128), 256, GEMM_SMEM>>>(
        pah, pal, pteh, ptel, nullptr, nullptr, logits, nullptr, nullptr, V, D);
}